// round 3
// baseline (speedup 1.0000x reference)
#include <cuda_runtime.h>
#include <cuda_bf16.h>
#include <math.h>

// ---------------------------------------------------------------------------
// Problem constants (shapes fixed by the dataset problem)
// ---------------------------------------------------------------------------
#define Bk     8
#define Hh     32
#define Ww     32
#define Lk     1024            // H*W
#define DIMk   512
#define DSk    16
#define DCONVk 4
#define DIk    1024            // 2*DIM
#define DTRk   32              // (DIM+15)/16
#define HIDk   1024            // 2*DIM
#define Mrows  (Bk*Lk)         // 8192

// ---------------------------------------------------------------------------
// Scratch (device globals; no allocation allowed in kernel_launch)
// ---------------------------------------------------------------------------
__device__ float g_pos_hidden[Lk * DIMk];
__device__ float g_pos[Lk * DIMk];
__device__ float g_scanin[Mrows * DIMk];
__device__ float g_xz[2ll * Mrows * (2 * DIk)];     // per dir: [8192][2048] (xin | z)
__device__ float g_xc[2ll * Mrows * DIk];
__device__ float g_proj[2ll * Mrows * 64];          // [dt(32) | B(16) | C(16)]
__device__ float g_delta[2ll * Mrows * DIk];
__device__ float g_ybuf[2ll * Mrows * DIk];
__device__ float g_dirout[2ll * Mrows * DIMk];
__device__ float g_cat[(long long)Mrows * (3 * DIMk)];
__device__ float g_mix[Mrows * DIMk];
__device__ float g_dln[Mrows * DIMk];
__device__ float g_x2[Mrows * DIMk];
__device__ float g_hbuf[Mrows * HIDk];

// ---------------------------------------------------------------------------
// Helpers
// ---------------------------------------------------------------------------
__device__ __forceinline__ float gelu_exact(float x) {
    return 0.5f * x * (1.0f + erff(x * 0.70710678118654752f));
}
__device__ __forceinline__ float silu(float x) {
    return x / (1.0f + __expf(-x));
}

__device__ __forceinline__ float block_reduce_sum_256(float v, float* sbuf) {
    int lane = threadIdx.x & 31, w = threadIdx.x >> 5;
    #pragma unroll
    for (int o = 16; o; o >>= 1) v += __shfl_down_sync(0xffffffffu, v, o);
    if (lane == 0) sbuf[w] = v;
    __syncthreads();
    float r = (threadIdx.x < 8) ? sbuf[threadIdx.x] : 0.0f;
    if (w == 0) {
        #pragma unroll
        for (int o = 4; o; o >>= 1) r += __shfl_down_sync(0xffu, r, o);
        if (lane == 0) sbuf[0] = r;
    }
    __syncthreads();
    float out = sbuf[0];
    __syncthreads();
    return out;
}

// ---------------------------------------------------------------------------
// Generic fp32 SGEMM:  C[M,N] = A[M,K(lda)] * W[N,K]^T  (+ epilogue)
// epi: 0 none, 1 +bias, 2 gelu(+bias), 3 +bias+resid, 4 softplus(+bias)
// rev: remap A row  l -> 1023-l  within each batch of 1024 rows
// ---------------------------------------------------------------------------
#define GT 128
#define GK 8

__global__ __launch_bounds__(256, 2)
void sgemm_kernel(const float* __restrict__ A, const float* __restrict__ W,
                  const float* __restrict__ bias, const float* __restrict__ resid,
                  float* __restrict__ C,
                  int M, int N, int K, int lda, int rev, int epi)
{
    __shared__ float As[GK][GT];
    __shared__ float Bs[GK][GT];

    const int tid = threadIdx.x;
    const int m0 = blockIdx.y * GT;
    const int n0 = blockIdx.x * GT;
    const int tx = tid & 15;        // 0..15 -> n sub-tile
    const int ty = tid >> 4;        // 0..15 -> m sub-tile

    const int la_m = tid & 127;
    const int la_k = (tid >> 7) << 2;   // 0 or 4
    const int lb_n = tid & 127;
    const int lb_k = (tid >> 7) << 2;

    int am = m0 + la_m;
    if (rev) am = (am & ~1023) + (1023 - (am & 1023));
    const float* Arow = A + (long long)am * lda;
    const bool wok = (n0 + lb_n) < N;
    const float* Wrow = wok ? (W + (long long)(n0 + lb_n) * K) : W;

    float acc[8][8];
    #pragma unroll
    for (int i = 0; i < 8; i++)
        #pragma unroll
        for (int j = 0; j < 8; j++) acc[i][j] = 0.0f;

    for (int k0 = 0; k0 < K; k0 += GK) {
        float4 av = *reinterpret_cast<const float4*>(Arow + k0 + la_k);
        float4 bv = make_float4(0.f, 0.f, 0.f, 0.f);
        if (wok) bv = *reinterpret_cast<const float4*>(Wrow + k0 + lb_k);
        __syncthreads();
        As[la_k + 0][la_m] = av.x; As[la_k + 1][la_m] = av.y;
        As[la_k + 2][la_m] = av.z; As[la_k + 3][la_m] = av.w;
        Bs[lb_k + 0][lb_n] = bv.x; Bs[lb_k + 1][lb_n] = bv.y;
        Bs[lb_k + 2][lb_n] = bv.z; Bs[lb_k + 3][lb_n] = bv.w;
        __syncthreads();

        #pragma unroll
        for (int k = 0; k < GK; k++) {
            float ra[8], rb[8];
            #pragma unroll
            for (int i = 0; i < 8; i++) ra[i] = As[k][ty * 8 + i];
            #pragma unroll
            for (int j = 0; j < 8; j++) rb[j] = Bs[k][tx * 8 + j];
            #pragma unroll
            for (int i = 0; i < 8; i++)
                #pragma unroll
                for (int j = 0; j < 8; j++) acc[i][j] = fmaf(ra[i], rb[j], acc[i][j]);
        }
    }

    #pragma unroll
    for (int i = 0; i < 8; i++) {
        int m = m0 + ty * 8 + i;
        #pragma unroll
        for (int j = 0; j < 8; j++) {
            int n = n0 + tx * 8 + j;
            if (n >= N) continue;
            float v = acc[i][j];
            if (epi >= 1) v += bias[n];
            if (epi == 2) v = gelu_exact(v);
            else if (epi == 3) v += resid[(long long)m * N + n];
            else if (epi == 4) v = (v > 20.0f) ? v : log1pf(__expf(v));
            C[(long long)m * N + n] = v;
        }
    }
}

// ---------------------------------------------------------------------------
// pos features: hidden[l][j] = gelu( pos6(l) . pos_w1[j] + pos_b1[j] )
// ---------------------------------------------------------------------------
__global__ void pos_feat_kernel(const float* __restrict__ w1, const float* __restrict__ b1,
                                float* __restrict__ hidden)
{
    const int l = blockIdx.x;
    const int j = threadIdx.x;
    const float PI = 3.14159265358979323846f;
    float yy = ((float)(l >> 5) + 0.5f) / (float)Hh * 2.0f - 1.0f;
    float xx = ((float)(l & 31) + 0.5f) / (float)Ww * 2.0f - 1.0f;
    float p0 = yy, p1 = xx;
    float p2 = sinf(PI * yy), p3 = cosf(PI * yy);
    float p4 = sinf(PI * xx), p5 = cosf(PI * xx);
    const float* w = w1 + j * 6;
    float a = p0 * w[0] + p1 * w[1] + p2 * w[2] + p3 * w[3] + p4 * w[4] + p5 * w[5] + b1[j];
    hidden[l * DIMk + j] = gelu_exact(a);
}

// ---------------------------------------------------------------------------
// scan_in = LN(tokens) + pos        (block per row; 256 threads, 2 cols each)
// ---------------------------------------------------------------------------
__global__ void ln_add_pos_kernel(const float* __restrict__ tokens,
                                  const float* __restrict__ g, const float* __restrict__ b,
                                  const float* __restrict__ pos, float* __restrict__ out)
{
    __shared__ float sbuf[8];
    const int m = blockIdx.x;
    const int l = m & (Lk - 1);
    const float* x = tokens + (long long)m * DIMk;
    int c0 = threadIdx.x, c1 = threadIdx.x + 256;
    float v0 = x[c0], v1 = x[c1];
    float mu = block_reduce_sum_256(v0 + v1, sbuf) * (1.0f / DIMk);
    float d0 = v0 - mu, d1 = v1 - mu;
    float var = block_reduce_sum_256(d0 * d0 + d1 * d1, sbuf) * (1.0f / DIMk);
    float inv = rsqrtf(var + 1e-5f);
    float* o = out + (long long)m * DIMk;
    o[c0] = d0 * inv * g[c0] + b[c0] + pos[l * DIMk + c0];
    o[c1] = d1 * inv * g[c1] + b[c1] + pos[l * DIMk + c1];
}

// ---------------------------------------------------------------------------
// causal depthwise conv (DCONV=4) + silu, both dirs
// ---------------------------------------------------------------------------
__global__ void conv_kernel(const float* __restrict__ cw, const float* __restrict__ cb)
{
    long long idx = (long long)blockIdx.x * blockDim.x + threadIdx.x;
    if (idx >= 2ll * Mrows * DIk) return;
    int d   = (int)(idx & (DIk - 1));
    long long m = idx >> 10;            // dir*8192 + b*1024 + l
    int dir = (int)(m >> 13);
    int bl  = (int)(m & (Mrows - 1));
    int l   = bl & (Lk - 1);
    const float* xin = g_xz + (long long)dir * Mrows * (2 * DIk);
    long long rowbase = (long long)bl * (2 * DIk) + d;
    const float* w = cw + ((long long)dir * DIk + d) * DCONVk;
    float acc = cb[dir * DIk + d];
    #pragma unroll
    for (int k = 0; k < DCONVk; k++) {
        int src = l - (DCONVk - 1) + k;
        if (src >= 0) acc += xin[rowbase + (long long)(src - l) * (2 * DIk)] * w[k];
    }
    g_xc[idx] = silu(acc);
}

// ---------------------------------------------------------------------------
// selective scan (sequential over L, parallel over dir,b,d)
// grid: 128 blocks (dir*64 + b*8 + dchunk), 128 threads (one d each)
// fused gating: y = (scan_y + xc*D) * silu(z)
// ---------------------------------------------------------------------------
__global__ __launch_bounds__(128, 1)
void scan_kernel(const float* __restrict__ A_log, const float* __restrict__ Dp)
{
    __shared__ float bc[2][32];
    const int blk = blockIdx.x;
    const int dir = blk >> 6;
    const int b   = (blk >> 3) & 7;
    const int d   = ((blk & 7) << 7) + threadIdx.x;

    const long long base = ((long long)dir * Mrows + (long long)b * Lk);
    const float* dl  = g_delta + base * DIk;
    const float* xcd = g_xc    + base * DIk;
    const float* pj  = g_proj  + base * 64;
    const float* zz  = g_xz    + base * (2 * DIk) + DIk;
    float*       yo  = g_ybuf  + base * DIk;

    float A[DSk];
    #pragma unroll
    for (int s = 0; s < DSk; s++)
        A[s] = -__expf(A_log[((long long)dir * DIk + d) * DSk + s]);
    const float Dv = Dp[dir * DIk + d];

    float h[DSk];
    #pragma unroll
    for (int s = 0; s < DSk; s++) h[s] = 0.0f;

    if (threadIdx.x < 32) bc[0][threadIdx.x] = pj[DTRk + threadIdx.x];
    __syncthreads();

    for (int t = 0; t < Lk; t++) {
        if (threadIdx.x < 32 && (t + 1) < Lk)
            bc[(t + 1) & 1][threadIdx.x] = pj[(long long)(t + 1) * 64 + DTRk + threadIdx.x];

        float dt = dl[(long long)t * DIk + d];
        float xt = xcd[(long long)t * DIk + d];
        const float* Bv = bc[t & 1];
        const float* Cv = bc[t & 1] + DSk;
        float dx = dt * xt;
        float y = 0.0f;
        #pragma unroll
        for (int s = 0; s < DSk; s++) {
            h[s] = h[s] * __expf(dt * A[s]) + dx * Bv[s];
            y = fmaf(h[s], Cv[s], y);
        }
        float zt = zz[(long long)t * (2 * DIk) + d];
        yo[(long long)t * DIk + d] = (y + xt * Dv) * silu(zt);
        __syncthreads();
    }
}

// ---------------------------------------------------------------------------
// concat [fwd | bwd(un-reversed) | pos] -> g_cat [8192][1536]
// ---------------------------------------------------------------------------
__global__ void cat_kernel()
{
    long long idx = (long long)blockIdx.x * blockDim.x + threadIdx.x;
    if (idx >= (long long)Mrows * 3 * DIMk) return;
    int c = (int)(idx % (3 * DIMk));
    int m = (int)(idx / (3 * DIMk));
    int b = m >> 10, l = m & (Lk - 1);
    float v;
    if (c < DIMk)            v = g_dirout[(long long)m * DIMk + c];
    else if (c < 2 * DIMk)   v = g_dirout[(long long)Mrows * DIMk +
                                          ((long long)(b * Lk + (Lk - 1 - l))) * DIMk + (c - DIMk)];
    else                     v = g_pos[l * DIMk + (c - 2 * DIMk)];
    g_cat[idx] = v;
}

// ---------------------------------------------------------------------------
// delta_ln = LN(mix, dn);  x2 = LN(delta_ln, fn)
// ---------------------------------------------------------------------------
__global__ void double_ln_kernel(const float* __restrict__ dng, const float* __restrict__ dnb,
                                 const float* __restrict__ fng, const float* __restrict__ fnb)
{
    __shared__ float sbuf[8];
    const int m = blockIdx.x;
    const float* x = g_mix + (long long)m * DIMk;
    int c0 = threadIdx.x, c1 = threadIdx.x + 256;
    float v0 = x[c0], v1 = x[c1];
    float mu = block_reduce_sum_256(v0 + v1, sbuf) * (1.0f / DIMk);
    float d0 = v0 - mu, d1 = v1 - mu;
    float var = block_reduce_sum_256(d0 * d0 + d1 * d1, sbuf) * (1.0f / DIMk);
    float inv = rsqrtf(var + 1e-5f);
    float e0 = d0 * inv * dng[c0] + dnb[c0];
    float e1 = d1 * inv * dng[c1] + dnb[c1];
    g_dln[(long long)m * DIMk + c0] = e0;
    g_dln[(long long)m * DIMk + c1] = e1;
    // second LN over (e0,e1) row
    float mu2 = block_reduce_sum_256(e0 + e1, sbuf) * (1.0f / DIMk);
    float f0 = e0 - mu2, f1 = e1 - mu2;
    float var2 = block_reduce_sum_256(f0 * f0 + f1 * f1, sbuf) * (1.0f / DIMk);
    float inv2 = rsqrtf(var2 + 1e-5f);
    g_x2[(long long)m * DIMk + c0] = f0 * inv2 * fng[c0] + fnb[c0];
    g_x2[(long long)m * DIMk + c1] = f1 * inv2 * fng[c1] + fnb[c1];
}

// ---------------------------------------------------------------------------
// launch
// ---------------------------------------------------------------------------
static inline float* dev_ptr(float* p) { return p; }

extern "C" void kernel_launch(void* const* d_in, const int* in_sizes, int n_in,
                              void* d_out, int out_size)
{
    const float* tokens   = (const float*)d_in[0];
    const float* in_g     = (const float*)d_in[3];
    const float* in_b     = (const float*)d_in[4];
    const float* pos_w1   = (const float*)d_in[5];
    const float* pos_b1   = (const float*)d_in[6];
    const float* pos_w2   = (const float*)d_in[7];
    const float* pos_b2   = (const float*)d_in[8];
    const float* m_in_w   = (const float*)d_in[9];
    const float* m_conv_w = (const float*)d_in[10];
    const float* m_conv_b = (const float*)d_in[11];
    const float* m_xproj_w= (const float*)d_in[12];
    const float* m_dt_w   = (const float*)d_in[13];
    const float* m_dt_b   = (const float*)d_in[14];
    const float* m_A_log  = (const float*)d_in[15];
    const float* m_D      = (const float*)d_in[16];
    const float* m_out_w  = (const float*)d_in[17];
    const float* mix_w    = (const float*)d_in[18];
    const float* mix_b    = (const float*)d_in[19];
    const float* dn_g     = (const float*)d_in[20];
    const float* dn_b     = (const float*)d_in[21];
    const float* fn_g     = (const float*)d_in[22];
    const float* fn_b     = (const float*)d_in[23];
    const float* ffn_w1   = (const float*)d_in[24];
    const float* ffn_b1   = (const float*)d_in[25];
    const float* ffn_w2   = (const float*)d_in[26];
    const float* ffn_b2   = (const float*)d_in[27];
    float* out = (float*)d_out;

    float *p_pos_hidden, *p_pos, *p_scanin, *p_xz, *p_xc, *p_proj, *p_delta,
          *p_ybuf, *p_dirout, *p_cat, *p_mix, *p_dln, *p_x2, *p_hbuf;
    cudaGetSymbolAddress((void**)&p_pos_hidden, g_pos_hidden);
    cudaGetSymbolAddress((void**)&p_pos,        g_pos);
    cudaGetSymbolAddress((void**)&p_scanin,     g_scanin);
    cudaGetSymbolAddress((void**)&p_xz,         g_xz);
    cudaGetSymbolAddress((void**)&p_xc,         g_xc);
    cudaGetSymbolAddress((void**)&p_proj,       g_proj);
    cudaGetSymbolAddress((void**)&p_delta,      g_delta);
    cudaGetSymbolAddress((void**)&p_ybuf,       g_ybuf);
    cudaGetSymbolAddress((void**)&p_dirout,     g_dirout);
    cudaGetSymbolAddress((void**)&p_cat,        g_cat);
    cudaGetSymbolAddress((void**)&p_mix,        g_mix);
    cudaGetSymbolAddress((void**)&p_dln,        g_dln);
    cudaGetSymbolAddress((void**)&p_x2,         g_x2);
    cudaGetSymbolAddress((void**)&p_hbuf,       g_hbuf);

    // 1) pos MLP
    pos_feat_kernel<<<Lk, DIMk>>>(pos_w1, pos_b1, p_pos_hidden);
    sgemm_kernel<<<dim3(DIMk/GT, Lk/GT), 256>>>(p_pos_hidden, pos_w2, pos_b2, nullptr,
                                                p_pos, Lk, DIMk, DIMk, DIMk, 0, 1);
    // 2) scan_in = LN(tokens)+pos
    ln_add_pos_kernel<<<Mrows, 256>>>(tokens, in_g, in_b, p_pos, p_scanin);

    // 3) in_proj (dir0 normal, dir1 row-reversed read)
    for (int dir = 0; dir < 2; dir++) {
        sgemm_kernel<<<dim3((2*DIk)/GT, Mrows/GT), 256>>>(
            p_scanin, m_in_w + (long long)dir * (2*DIk) * DIMk, nullptr, nullptr,
            p_xz + (long long)dir * Mrows * (2*DIk),
            Mrows, 2*DIk, DIMk, DIMk, dir, 0);
    }
    // 4) conv + silu (both dirs)
    {
        long long tot = 2ll * Mrows * DIk;
        conv_kernel<<<(unsigned)((tot + 255) / 256), 256>>>(m_conv_w, m_conv_b);
    }
    // 5) x_proj ; 6) dt proj + softplus
    for (int dir = 0; dir < 2; dir++) {
        sgemm_kernel<<<dim3(1, Mrows/GT), 256>>>(
            p_xc + (long long)dir * Mrows * DIk, m_xproj_w + (long long)dir * 64 * DIk,
            nullptr, nullptr, p_proj + (long long)dir * Mrows * 64,
            Mrows, 64, DIk, DIk, 0, 0);
        sgemm_kernel<<<dim3(DIk/GT, Mrows/GT), 256>>>(
            p_proj + (long long)dir * Mrows * 64, m_dt_w + (long long)dir * DIk * DTRk,
            m_dt_b + dir * DIk, nullptr, p_delta + (long long)dir * Mrows * DIk,
            Mrows, DIk, DTRk, 64, 0, 4);
    }
    // 7) selective scan + gating
    scan_kernel<<<128, 128>>>(m_A_log, m_D);

    // 8) out_proj
    for (int dir = 0; dir < 2; dir++) {
        sgemm_kernel<<<dim3(DIMk/GT, Mrows/GT), 256>>>(
            p_ybuf + (long long)dir * Mrows * DIk, m_out_w + (long long)dir * DIMk * DIk,
            nullptr, nullptr, p_dirout + (long long)dir * Mrows * DIMk,
            Mrows, DIMk, DIk, DIk, 0, 0);
    }
    // 9) concat + 10) mix GEMM
    {
        long long tot = (long long)Mrows * 3 * DIMk;
        cat_kernel<<<(unsigned)((tot + 255) / 256), 256>>>();
    }
    sgemm_kernel<<<dim3(DIMk/GT, Mrows/GT), 256>>>(p_cat, mix_w, mix_b, nullptr,
                                                   p_mix, Mrows, DIMk, 3*DIMk, 3*DIMk, 0, 1);
    // 11) double LN
    double_ln_kernel<<<Mrows, 256>>>(dn_g, dn_b, fn_g, fn_b);

    // 12) FFN
    sgemm_kernel<<<dim3(HIDk/GT, Mrows/GT), 256>>>(p_x2, ffn_w1, ffn_b1, nullptr,
                                                   p_hbuf, Mrows, HIDk, DIMk, DIMk, 0, 2);
    sgemm_kernel<<<dim3(DIMk/GT, Mrows/GT), 256>>>(p_hbuf, ffn_w2, ffn_b2, p_dln,
                                                   out, Mrows, DIMk, HIDk, HIDk, 0, 3);
    (void)in_sizes; (void)n_in; (void)out_size; (void)dev_ptr;
}

// round 5
// speedup vs baseline: 1.7564x; 1.7564x over previous
#include <cuda_runtime.h>
#include <cuda_bf16.h>
#include <math.h>
#include <stdint.h>

// ---------------------------------------------------------------------------
// Problem constants
// ---------------------------------------------------------------------------
#define Bk     8
#define Hh     32
#define Ww     32
#define Lk     1024
#define DIMk   512
#define DSk    16
#define DCONVk 4
#define DIk    1024
#define DTRk   32
#define HIDk   1024
#define Mrows  (Bk*Lk)          // 8192

// ---------------------------------------------------------------------------
// Scratch (device globals)
// ---------------------------------------------------------------------------
__device__ float g_pos_hidden[Lk * DIMk];
__device__ float g_pos[Lk * DIMk];
__device__ float g_scanin[Mrows * DIMk];
__device__ float g_xz[2ll * Mrows * (2 * DIk)];
__device__ float g_xc[2ll * Mrows * DIk];
__device__ float g_proj[2ll * Mrows * 64];
__device__ float g_delta[2ll * Mrows * DIk];
__device__ float g_ybuf[2ll * Mrows * DIk];
__device__ float g_cat[(long long)Mrows * (3 * DIMk)];
__device__ float g_mix[Mrows * DIMk];
__device__ float g_dln[Mrows * DIMk];
__device__ float g_x2[Mrows * DIMk];
__device__ float g_hbuf[Mrows * HIDk];

// ---------------------------------------------------------------------------
// Low-level helpers (sm_80-era PTX only; NO tcgen05 — target is sm_103)
// ---------------------------------------------------------------------------
__device__ __forceinline__ uint32_t smem_to_u32(const void* p) {
    uint32_t a;
    asm("{ .reg .u64 t; cvta.to.shared.u64 t, %1; cvt.u32.u64 %0, t; }" : "=r"(a) : "l"(p));
    return a;
}
__device__ __forceinline__ void ldsm4(uint32_t* r, uint32_t addr) {
    asm volatile("ldmatrix.sync.aligned.m8n8.x4.shared.b16 {%0,%1,%2,%3}, [%4];"
                 : "=r"(r[0]), "=r"(r[1]), "=r"(r[2]), "=r"(r[3]) : "r"(addr));
}
__device__ __forceinline__ void mma_bf16(float* c, const uint32_t* a, uint32_t b0, uint32_t b1) {
    asm volatile("mma.sync.aligned.m16n8k16.row.col.f32.bf16.bf16.f32 "
                 "{%0,%1,%2,%3}, {%4,%5,%6,%7}, {%8,%9}, {%0,%1,%2,%3};"
                 : "+f"(c[0]), "+f"(c[1]), "+f"(c[2]), "+f"(c[3])
                 : "r"(a[0]), "r"(a[1]), "r"(a[2]), "r"(a[3]), "r"(b0), "r"(b1));
}
__device__ __forceinline__ uint32_t bf16pack(float e0, float e1) { // e0 -> low half
    uint32_t r; asm("cvt.rn.bf16x2.f32 %0, %1, %2;" : "=r"(r) : "f"(e1), "f"(e0)); return r;
}
__device__ __forceinline__ float bf16lo_as_f32(uint32_t p) { return __uint_as_float(p << 16); }
__device__ __forceinline__ float bf16hi_as_f32(uint32_t p) { return __uint_as_float(p & 0xffff0000u); }

__device__ __forceinline__ float gelu_exact(float x) {
    return 0.5f * x * (1.0f + erff(x * 0.70710678118654752f));
}
__device__ __forceinline__ float silu(float x) { return x / (1.0f + __expf(-x)); }

__device__ __forceinline__ float block_reduce_sum_256(float v, float* sbuf) {
    int lane = threadIdx.x & 31, w = threadIdx.x >> 5;
    #pragma unroll
    for (int o = 16; o; o >>= 1) v += __shfl_down_sync(0xffffffffu, v, o);
    if (lane == 0) sbuf[w] = v;
    __syncthreads();
    float r = (threadIdx.x < 8) ? sbuf[threadIdx.x] : 0.0f;
    if (w == 0) {
        #pragma unroll
        for (int o = 4; o; o >>= 1) r += __shfl_down_sync(0xffu, r, o);
        if (lane == 0) sbuf[0] = r;
    }
    __syncthreads();
    float out = sbuf[0];
    __syncthreads();
    return out;
}

// ---------------------------------------------------------------------------
// mma.sync bf16x3 GEMM:  C[M,N] = A[M,K] * W[N,K]^T  (fp32 in/out)
//  block tile 128x128, kc=32, double-buffered smem (bf16 hi/lo planes)
//  smem plane layout: row stride 40 b16 (80 B); Ahi@0 Alo@10240 Bhi@20480 Blo@30720
//  epi: 0 none, 1 +bias, 2 gelu(+bias), 3 +bias+resid, 4 softplus(+bias)
//  arev/crev: reverse row index within 1024-row batches on A read / C write
// ---------------------------------------------------------------------------
#define KC    32
#define BUFB  40960
#define TCG_SMEM_BYTES (2 * BUFB)

struct Stage { float4 a[4]; float4 b[4]; };

__device__ __forceinline__ void ldg_stage(Stage& st, const float* __restrict__ A,
                                          const float* __restrict__ W,
                                          int m0, int n0, int N, int K, int lda,
                                          int arev, int k0, int tid)
{
    #pragma unroll
    for (int it = 0; it < 2; it++) {
        int task = tid + it * 256;
        int row = task >> 2, kg = task & 3;
        int gm = m0 + row;
        if (arev) gm = (gm & ~(Lk - 1)) + (Lk - 1 - (gm & (Lk - 1)));
        const float* s = A + (long long)gm * lda + k0 + kg * 8;
        st.a[it * 2]     = *reinterpret_cast<const float4*>(s);
        st.a[it * 2 + 1] = *reinterpret_cast<const float4*>(s + 4);
        int gn = n0 + row;
        if (gn < N) {
            const float* t = W + (long long)gn * K + k0 + kg * 8;
            st.b[it * 2]     = *reinterpret_cast<const float4*>(t);
            st.b[it * 2 + 1] = *reinterpret_cast<const float4*>(t + 4);
        } else {
            st.b[it * 2]     = make_float4(0.f, 0.f, 0.f, 0.f);
            st.b[it * 2 + 1] = make_float4(0.f, 0.f, 0.f, 0.f);
        }
    }
}

__device__ __forceinline__ void cvt8(char* hid, char* lod, float4 p, float4 q)
{
    uint4 hi, lo;
    hi.x = bf16pack(p.x, p.y); hi.y = bf16pack(p.z, p.w);
    hi.z = bf16pack(q.x, q.y); hi.w = bf16pack(q.z, q.w);
    lo.x = bf16pack(p.x - bf16lo_as_f32(hi.x), p.y - bf16hi_as_f32(hi.x));
    lo.y = bf16pack(p.z - bf16lo_as_f32(hi.y), p.w - bf16hi_as_f32(hi.y));
    lo.z = bf16pack(q.x - bf16lo_as_f32(hi.z), q.y - bf16hi_as_f32(hi.z));
    lo.w = bf16pack(q.z - bf16lo_as_f32(hi.w), q.w - bf16hi_as_f32(hi.w));
    *reinterpret_cast<uint4*>(hid) = hi;
    *reinterpret_cast<uint4*>(lod) = lo;
}

__device__ __forceinline__ void sts_stage(const Stage& st, char* buf, int tid)
{
    #pragma unroll
    for (int it = 0; it < 2; it++) {
        int task = tid + it * 256;
        int row = task >> 2, kg = task & 3;
        uint32_t off = (uint32_t)(row * 80 + kg * 16);
        cvt8(buf + off,         buf + 10240 + off, st.a[it * 2], st.a[it * 2 + 1]);
        cvt8(buf + 20480 + off, buf + 30720 + off, st.b[it * 2], st.b[it * 2 + 1]);
    }
}

__device__ __forceinline__ void compute_chunk(float acc[4][4][4], uint32_t base,
                                              int warpM, int warpN, int lane)
{
    const uint32_t rsel = (uint32_t)(lane & 15);
    const uint32_t ksel = (uint32_t)(lane >> 4);    // 0/1 -> +8 k elements
    #pragma unroll
    for (int pass = 0; pass < 3; pass++) {
        uint32_t Ab = base + ((pass == 2) ? 10240u : 0u);
        uint32_t Bb = base + 20480u + ((pass == 1) ? 10240u : 0u);
        #pragma unroll
        for (int ks = 0; ks < 2; ks++) {
            uint32_t koff = (uint32_t)(ks * 2 + ksel) * 16u;
            uint32_t a[4][4];
            #pragma unroll
            for (int mt = 0; mt < 4; mt++)
                ldsm4(a[mt], Ab + (uint32_t)(warpM + mt * 16 + rsel) * 80u + koff);
            uint32_t b[2][4];
            #pragma unroll
            for (int p = 0; p < 2; p++)
                ldsm4(b[p], Bb + (uint32_t)(warpN + p * 16 + rsel) * 80u + koff);
            #pragma unroll
            for (int mt = 0; mt < 4; mt++)
                #pragma unroll
                for (int nt = 0; nt < 4; nt++)
                    mma_bf16(acc[mt][nt], a[mt], b[nt >> 1][nt & 1], b[nt >> 1][2 + (nt & 1)]);
        }
    }
}

__global__ __launch_bounds__(256)
void tc_gemm(const float* __restrict__ A, const float* __restrict__ W,
             const float* __restrict__ bias, const float* __restrict__ resid,
             float* __restrict__ C,
             int M, int N, int K, int lda, int ldc,
             int arev, int crev, int epi)
{
    extern __shared__ char smem[];
    const uint32_t sb = smem_to_u32(smem);
    const int tid = threadIdx.x, lane = tid & 31, wid = tid >> 5;
    const int m0 = blockIdx.y * 128, n0 = blockIdx.x * 128;
    const int warpM = (wid & 1) * 64, warpN = (wid >> 1) * 32;

    float acc[4][4][4];
    #pragma unroll
    for (int i = 0; i < 4; i++)
        #pragma unroll
        for (int j = 0; j < 4; j++)
            #pragma unroll
            for (int r = 0; r < 4; r++) acc[i][j][r] = 0.0f;

    const int nch = K / KC;

    Stage st;
    ldg_stage(st, A, W, m0, n0, N, K, lda, arev, 0, tid);
    sts_stage(st, smem, tid);
    __syncthreads();

    for (int c = 0; c < nch; c++) {
        if (c + 1 < nch)
            ldg_stage(st, A, W, m0, n0, N, K, lda, arev, (c + 1) * KC, tid);
        compute_chunk(acc, sb + (uint32_t)(c & 1) * BUFB, warpM, warpN, lane);
        if (c + 1 < nch)
            sts_stage(st, smem + ((c + 1) & 1) * BUFB, tid);
        __syncthreads();
    }

    // ---- epilogue: fragment -> global (float2 per thread-pair) ----
    #pragma unroll
    for (int mt = 0; mt < 4; mt++) {
        int r0 = m0 + warpM + mt * 16 + (lane >> 2);
        #pragma unroll
        for (int half = 0; half < 2; half++) {
            int gm = r0 + half * 8;
            if (crev) gm = (gm & ~(Lk - 1)) + (Lk - 1 - (gm & (Lk - 1)));
            #pragma unroll
            for (int nt = 0; nt < 4; nt++) {
                int col = n0 + warpN + nt * 8 + (lane & 3) * 2;
                if (col >= N) continue;
                float v0 = acc[mt][nt][half * 2 + 0];
                float v1 = acc[mt][nt][half * 2 + 1];
                if (epi >= 1) { v0 += bias[col]; v1 += bias[col + 1]; }
                if (epi == 2) { v0 = gelu_exact(v0); v1 = gelu_exact(v1); }
                else if (epi == 4) {
                    v0 = (v0 > 20.0f) ? v0 : log1pf(__expf(v0));
                    v1 = (v1 > 20.0f) ? v1 : log1pf(__expf(v1));
                } else if (epi == 3) {
                    const float* rp = resid + (long long)gm * ldc + col;
                    v0 += rp[0]; v1 += rp[1];
                }
                *reinterpret_cast<float2*>(C + (long long)gm * ldc + col) =
                    make_float2(v0, v1);
            }
        }
    }
}

// ---------------------------------------------------------------------------
// pos features
// ---------------------------------------------------------------------------
__global__ void pos_feat_kernel(const float* __restrict__ w1, const float* __restrict__ b1,
                                float* __restrict__ hidden)
{
    const int l = blockIdx.x;
    const int j = threadIdx.x;
    const float PI = 3.14159265358979323846f;
    float yy = ((float)(l >> 5) + 0.5f) / (float)Hh * 2.0f - 1.0f;
    float xx = ((float)(l & 31) + 0.5f) / (float)Ww * 2.0f - 1.0f;
    float p2 = sinf(PI * yy), p3 = cosf(PI * yy);
    float p4 = sinf(PI * xx), p5 = cosf(PI * xx);
    const float* w = w1 + j * 6;
    float a = yy * w[0] + xx * w[1] + p2 * w[2] + p3 * w[3] + p4 * w[4] + p5 * w[5] + b1[j];
    hidden[l * DIMk + j] = gelu_exact(a);
}

// ---------------------------------------------------------------------------
// scan_in = LN(tokens) + pos
// ---------------------------------------------------------------------------
__global__ void ln_add_pos_kernel(const float* __restrict__ tokens,
                                  const float* __restrict__ g, const float* __restrict__ b,
                                  const float* __restrict__ pos, float* __restrict__ out)
{
    __shared__ float sbuf[8];
    const int m = blockIdx.x;
    const int l = m & (Lk - 1);
    const float* x = tokens + (long long)m * DIMk;
    int c0 = threadIdx.x, c1 = threadIdx.x + 256;
    float v0 = x[c0], v1 = x[c1];
    float mu = block_reduce_sum_256(v0 + v1, sbuf) * (1.0f / DIMk);
    float d0 = v0 - mu, d1 = v1 - mu;
    float var = block_reduce_sum_256(d0 * d0 + d1 * d1, sbuf) * (1.0f / DIMk);
    float inv = rsqrtf(var + 1e-5f);
    float* o = out + (long long)m * DIMk;
    o[c0] = d0 * inv * g[c0] + b[c0] + pos[l * DIMk + c0];
    o[c1] = d1 * inv * g[c1] + b[c1] + pos[l * DIMk + c1];
}

// ---------------------------------------------------------------------------
// causal depthwise conv + silu
// ---------------------------------------------------------------------------
__global__ void conv_kernel(const float* __restrict__ cw, const float* __restrict__ cb)
{
    long long idx = (long long)blockIdx.x * blockDim.x + threadIdx.x;
    if (idx >= 2ll * Mrows * DIk) return;
    int d   = (int)(idx & (DIk - 1));
    long long m = idx >> 10;
    int dir = (int)(m >> 13);
    int bl  = (int)(m & (Mrows - 1));
    int l   = bl & (Lk - 1);
    const float* xin = g_xz + (long long)dir * Mrows * (2 * DIk);
    long long rowbase = (long long)bl * (2 * DIk) + d;
    const float* w = cw + ((long long)dir * DIk + d) * DCONVk;
    float acc = cb[dir * DIk + d];
    #pragma unroll
    for (int k = 0; k < DCONVk; k++) {
        int src = l - (DCONVk - 1) + k;
        if (src >= 0) acc += xin[rowbase + (long long)(src - l) * (2 * DIk)] * w[k];
    }
    g_xc[idx] = silu(acc);
}

// ---------------------------------------------------------------------------
// selective scan: shuffle-broadcast B/C, ring-4 prefetch, fast exp path
// ---------------------------------------------------------------------------
__global__ __launch_bounds__(128, 8)
void scan_kernel(const float* __restrict__ A_log, const float* __restrict__ Dp)
{
    const int blk = blockIdx.x;
    const int dir = blk >> 6;
    const int b   = (blk >> 3) & 7;
    const int d   = ((blk & 7) << 7) + threadIdx.x;
    const int lane = threadIdx.x & 31;

    const long long base = ((long long)dir * Mrows + (long long)b * Lk);
    const float* dl  = g_delta + base * DIk + d;
    const float* xcd = g_xc    + base * DIk + d;
    const float* pj  = g_proj  + base * 64 + DTRk + lane;
    const float* zz  = g_xz    + base * (2 * DIk) + DIk + d;
    float*       yo  = g_ybuf  + base * DIk + d;

    float A[DSk];
    bool fast = true;
    #pragma unroll
    for (int s = 0; s < DSk; s++) {
        A[s] = -expf(A_log[((long long)dir * DIk + d) * DSk + s]);
        float t = (float)(s + 1);
        if (fabsf(A[s] + t) > 1e-4f * t) fast = false;
    }
    const float Dv = Dp[dir * DIk + d];
    float h[DSk];
    #pragma unroll
    for (int s = 0; s < DSk; s++) h[s] = 0.0f;

    float rdt[4], rxt[4], rzt[4], rbc[4];
    #pragma unroll
    for (int j = 0; j < 4; j++) {
        rdt[j] = dl[(long long)j * DIk];
        rxt[j] = xcd[(long long)j * DIk];
        rzt[j] = zz[(long long)j * (2 * DIk)];
        rbc[j] = pj[(long long)j * 64];
    }

    for (int t = 0; t < Lk; t += 4) {
        #pragma unroll
        for (int j = 0; j < 4; j++) {
            float dt = rdt[j], xt = rxt[j], zt = rzt[j], bcv = rbc[j];
            int tn = t + j + 4;
            if (tn < Lk) {
                rdt[j] = dl[(long long)tn * DIk];
                rxt[j] = xcd[(long long)tn * DIk];
                rzt[j] = zz[(long long)tn * (2 * DIk)];
                rbc[j] = pj[(long long)tn * 64];
            }
            float dx = dt * xt;
            float y = 0.0f;
            if (fast) {
                float e1 = __expf(-dt);
                float w = e1;
                #pragma unroll
                for (int s = 0; s < DSk; s++) {
                    float Bs = __shfl_sync(0xffffffffu, bcv, s);
                    float Cs = __shfl_sync(0xffffffffu, bcv, 16 + s);
                    h[s] = h[s] * w + dx * Bs;
                    y = fmaf(h[s], Cs, y);
                    w *= e1;
                }
            } else {
                #pragma unroll
                for (int s = 0; s < DSk; s++) {
                    float Bs = __shfl_sync(0xffffffffu, bcv, s);
                    float Cs = __shfl_sync(0xffffffffu, bcv, 16 + s);
                    h[s] = h[s] * __expf(dt * A[s]) + dx * Bs;
                    y = fmaf(h[s], Cs, y);
                }
            }
            yo[(long long)(t + j) * DIk] = (y + xt * Dv) * silu(zt);
        }
    }
}

// ---------------------------------------------------------------------------
// broadcast pos into g_cat[:, 1024:1536]
// ---------------------------------------------------------------------------
__global__ void posbc_kernel()
{
    long long idx = (long long)blockIdx.x * blockDim.x + threadIdx.x;
    int c = (int)(idx & (DIMk - 1));
    int m = (int)(idx >> 9);
    int l = m & (Lk - 1);
    g_cat[(long long)m * (3 * DIMk) + 2 * DIMk + c] = g_pos[l * DIMk + c];
}

// ---------------------------------------------------------------------------
// delta_ln = LN(mix, dn);  x2 = LN(delta_ln, fn)
// ---------------------------------------------------------------------------
__global__ void double_ln_kernel(const float* __restrict__ dng, const float* __restrict__ dnb,
                                 const float* __restrict__ fng, const float* __restrict__ fnb)
{
    __shared__ float sbuf[8];
    const int m = blockIdx.x;
    const float* x = g_mix + (long long)m * DIMk;
    int c0 = threadIdx.x, c1 = threadIdx.x + 256;
    float v0 = x[c0], v1 = x[c1];
    float mu = block_reduce_sum_256(v0 + v1, sbuf) * (1.0f / DIMk);
    float d0 = v0 - mu, d1 = v1 - mu;
    float var = block_reduce_sum_256(d0 * d0 + d1 * d1, sbuf) * (1.0f / DIMk);
    float inv = rsqrtf(var + 1e-5f);
    float e0 = d0 * inv * dng[c0] + dnb[c0];
    float e1 = d1 * inv * dng[c1] + dnb[c1];
    g_dln[(long long)m * DIMk + c0] = e0;
    g_dln[(long long)m * DIMk + c1] = e1;
    float mu2 = block_reduce_sum_256(e0 + e1, sbuf) * (1.0f / DIMk);
    float f0 = e0 - mu2, f1 = e1 - mu2;
    float var2 = block_reduce_sum_256(f0 * f0 + f1 * f1, sbuf) * (1.0f / DIMk);
    float inv2 = rsqrtf(var2 + 1e-5f);
    g_x2[(long long)m * DIMk + c0] = f0 * inv2 * fng[c0] + fnb[c0];
    g_x2[(long long)m * DIMk + c1] = f1 * inv2 * fng[c1] + fnb[c1];
}

// ---------------------------------------------------------------------------
// launch
// ---------------------------------------------------------------------------
extern "C" void kernel_launch(void* const* d_in, const int* in_sizes, int n_in,
                              void* d_out, int out_size)
{
    const float* tokens   = (const float*)d_in[0];
    const float* in_g     = (const float*)d_in[3];
    const float* in_b     = (const float*)d_in[4];
    const float* pos_w1   = (const float*)d_in[5];
    const float* pos_b1   = (const float*)d_in[6];
    const float* pos_w2   = (const float*)d_in[7];
    const float* pos_b2   = (const float*)d_in[8];
    const float* m_in_w   = (const float*)d_in[9];
    const float* m_conv_w = (const float*)d_in[10];
    const float* m_conv_b = (const float*)d_in[11];
    const float* m_xproj_w= (const float*)d_in[12];
    const float* m_dt_w   = (const float*)d_in[13];
    const float* m_dt_b   = (const float*)d_in[14];
    const float* m_A_log  = (const float*)d_in[15];
    const float* m_D      = (const float*)d_in[16];
    const float* m_out_w  = (const float*)d_in[17];
    const float* mix_w    = (const float*)d_in[18];
    const float* mix_b    = (const float*)d_in[19];
    const float* dn_g     = (const float*)d_in[20];
    const float* dn_b     = (const float*)d_in[21];
    const float* fn_g     = (const float*)d_in[22];
    const float* fn_b     = (const float*)d_in[23];
    const float* ffn_w1   = (const float*)d_in[24];
    const float* ffn_b1   = (const float*)d_in[25];
    const float* ffn_w2   = (const float*)d_in[26];
    const float* ffn_b2   = (const float*)d_in[27];
    float* out = (float*)d_out;

    float *p_pos_hidden, *p_pos, *p_scanin, *p_xz, *p_xc, *p_proj, *p_delta,
          *p_ybuf, *p_cat, *p_mix, *p_dln, *p_x2, *p_hbuf;
    cudaGetSymbolAddress((void**)&p_pos_hidden, g_pos_hidden);
    cudaGetSymbolAddress((void**)&p_pos,        g_pos);
    cudaGetSymbolAddress((void**)&p_scanin,     g_scanin);
    cudaGetSymbolAddress((void**)&p_xz,         g_xz);
    cudaGetSymbolAddress((void**)&p_xc,         g_xc);
    cudaGetSymbolAddress((void**)&p_proj,       g_proj);
    cudaGetSymbolAddress((void**)&p_delta,      g_delta);
    cudaGetSymbolAddress((void**)&p_ybuf,       g_ybuf);
    cudaGetSymbolAddress((void**)&p_cat,        g_cat);
    cudaGetSymbolAddress((void**)&p_mix,        g_mix);
    cudaGetSymbolAddress((void**)&p_dln,        g_dln);
    cudaGetSymbolAddress((void**)&p_x2,         g_x2);
    cudaGetSymbolAddress((void**)&p_hbuf,       g_hbuf);

    static int smem_set = 0;
    if (!smem_set) {
        cudaFuncSetAttribute(tc_gemm, cudaFuncAttributeMaxDynamicSharedMemorySize, TCG_SMEM_BYTES);
        smem_set = 1;
    }
    const int SB = TCG_SMEM_BYTES;

    // 1) pos MLP
    pos_feat_kernel<<<Lk, DIMk>>>(pos_w1, pos_b1, p_pos_hidden);
    tc_gemm<<<dim3(4, 8), 256, SB>>>(p_pos_hidden, pos_w2, pos_b2, nullptr, p_pos,
                                     Lk, DIMk, DIMk, DIMk, DIMk, 0, 0, 1);
    // 2) scan_in = LN(tokens)+pos
    ln_add_pos_kernel<<<Mrows, 256>>>(tokens, in_g, in_b, p_pos, p_scanin);

    // 3) in_proj (dir1 reads rows reversed)
    for (int dir = 0; dir < 2; dir++) {
        tc_gemm<<<dim3(16, 64), 256, SB>>>(
            p_scanin, m_in_w + (long long)dir * (2 * DIk) * DIMk, nullptr, nullptr,
            p_xz + (long long)dir * Mrows * (2 * DIk),
            Mrows, 2 * DIk, DIMk, DIMk, 2 * DIk, dir, 0, 0);
    }
    // 4) conv + silu
    conv_kernel<<<(unsigned)((2ll * Mrows * DIk + 255) / 256), 256>>>(m_conv_w, m_conv_b);

    // 5) x_proj (N=64, guarded), 6) dt proj + softplus (K=32)
    for (int dir = 0; dir < 2; dir++) {
        tc_gemm<<<dim3(1, 64), 256, SB>>>(
            p_xc + (long long)dir * Mrows * DIk, m_xproj_w + (long long)dir * 64 * DIk,
            nullptr, nullptr, p_proj + (long long)dir * Mrows * 64,
            Mrows, 64, DIk, DIk, 64, 0, 0, 0);
        tc_gemm<<<dim3(8, 64), 256, SB>>>(
            p_proj + (long long)dir * Mrows * 64, m_dt_w + (long long)dir * DIk * DTRk,
            m_dt_b + dir * DIk, nullptr, p_delta + (long long)dir * Mrows * DIk,
            Mrows, DIk, DTRk, 64, DIk, 0, 0, 4);
    }
    // 7) selective scan + gating
    scan_kernel<<<128, 128>>>(m_A_log, m_D);

    // 8) out_proj -> writes directly into g_cat slices (bwd un-reversed on store)
    for (int dir = 0; dir < 2; dir++) {
        tc_gemm<<<dim3(4, 64), 256, SB>>>(
            p_ybuf + (long long)dir * Mrows * DIk, m_out_w + (long long)dir * DIMk * DIk,
            nullptr, nullptr, p_cat + dir * DIMk,
            Mrows, DIMk, DIk, DIk, 3 * DIMk, 0, dir, 0);
    }
    // 9) pos broadcast into cat third slice
    posbc_kernel<<<(unsigned)(((long long)Mrows * DIMk + 255) / 256), 256>>>();

    // 10) mix GEMM
    tc_gemm<<<dim3(4, 64), 256, SB>>>(p_cat, mix_w, mix_b, nullptr, p_mix,
                                      Mrows, DIMk, 3 * DIMk, 3 * DIMk, DIMk, 0, 0, 1);
    // 11) double LN
    double_ln_kernel<<<Mrows, 256>>>(dn_g, dn_b, fn_g, fn_b);

    // 12) FFN
    tc_gemm<<<dim3(8, 64), 256, SB>>>(p_x2, ffn_w1, ffn_b1, nullptr, p_hbuf,
                                      Mrows, HIDk, DIMk, DIMk, HIDk, 0, 0, 2);
    tc_gemm<<<dim3(4, 64), 256, SB>>>(p_hbuf, ffn_w2, ffn_b2, p_dln, out,
                                      Mrows, DIMk, HIDk, HIDk, DIMk, 0, 0, 3);
    (void)in_sizes; (void)n_in; (void)out_size;
}

// round 10
// speedup vs baseline: 1.8169x; 1.0344x over previous
#include <cuda_runtime.h>
#include <cuda_bf16.h>
#include <math.h>
#include <stdint.h>

// ---------------------------------------------------------------------------
// Problem constants
// ---------------------------------------------------------------------------
#define Bk     8
#define Hh     32
#define Ww     32
#define Lk     1024
#define DIMk   512
#define DSk    16
#define DCONVk 4
#define DIk    1024
#define DTRk   32
#define HIDk   1024
#define Mrows  (Bk*Lk)          // 8192

// ---------------------------------------------------------------------------
// fp32 scratch (still needed by scan / conv / resid paths)
// ---------------------------------------------------------------------------
__device__ float g_pos[Lk * DIMk];
__device__ float g_xz[2ll * Mrows * (2 * DIk)];
__device__ float g_xc[2ll * Mrows * DIk];
__device__ float g_proj[2ll * Mrows * 64];
__device__ float g_delta[2ll * Mrows * DIk];
__device__ float g_mix[Mrows * DIMk];
__device__ float g_dln[Mrows * DIMk];

// ---------------------------------------------------------------------------
// bf16 hi/lo split buffers: layout [hi plane (n elems) | lo plane (n elems)]
// ---------------------------------------------------------------------------
__device__ __nv_bfloat16 b_posh [2ll * Lk * DIMk];
__device__ __nv_bfloat16 b_scanin[2ll * Mrows * DIMk];
__device__ __nv_bfloat16 b_xc  [2ll * 2 * Mrows * DIk];
__device__ __nv_bfloat16 b_proj[2ll * 2 * Mrows * 64];
__device__ __nv_bfloat16 b_ybuf[2ll * 2 * Mrows * DIk];
__device__ __nv_bfloat16 b_cat [2ll * Mrows * 3 * DIMk];
__device__ __nv_bfloat16 b_x2  [2ll * Mrows * DIMk];
__device__ __nv_bfloat16 b_hbuf[2ll * Mrows * HIDk];
// weights
__device__ __nv_bfloat16 b_posw2 [2ll * DIMk * DIMk];
__device__ __nv_bfloat16 b_inw   [2ll * 2 * (2 * DIk) * DIMk];
__device__ __nv_bfloat16 b_xprojw[2ll * 2 * 64 * DIk];
__device__ __nv_bfloat16 b_dtw   [2ll * 2 * DIk * DTRk];
__device__ __nv_bfloat16 b_outw  [2ll * 2 * DIMk * DIk];
__device__ __nv_bfloat16 b_mixw  [2ll * DIMk * 3 * DIMk];
__device__ __nv_bfloat16 b_ffn1w [2ll * HIDk * DIMk];
__device__ __nv_bfloat16 b_ffn2w [2ll * DIMk * HIDk];

// ---------------------------------------------------------------------------
// Helpers (sm_80-era PTX only)
// ---------------------------------------------------------------------------
__device__ __forceinline__ uint32_t smem_to_u32(const void* p) {
    uint32_t a;
    asm("{ .reg .u64 t; cvta.to.shared.u64 t, %1; cvt.u32.u64 %0, t; }" : "=r"(a) : "l"(p));
    return a;
}
__device__ __forceinline__ void ldsm4(uint32_t* r, uint32_t addr) {
    asm volatile("ldmatrix.sync.aligned.m8n8.x4.shared.b16 {%0,%1,%2,%3}, [%4];"
                 : "=r"(r[0]), "=r"(r[1]), "=r"(r[2]), "=r"(r[3]) : "r"(addr));
}
__device__ __forceinline__ void mma_bf16(float* c, const uint32_t* a, uint32_t b0, uint32_t b1) {
    asm volatile("mma.sync.aligned.m16n8k16.row.col.f32.bf16.bf16.f32 "
                 "{%0,%1,%2,%3}, {%4,%5,%6,%7}, {%8,%9}, {%0,%1,%2,%3};"
                 : "+f"(c[0]), "+f"(c[1]), "+f"(c[2]), "+f"(c[3])
                 : "r"(a[0]), "r"(a[1]), "r"(a[2]), "r"(a[3]), "r"(b0), "r"(b1));
}
__device__ __forceinline__ void cp_async16(uint32_t dst, const void* src, int srcsize) {
    asm volatile("cp.async.ca.shared.global [%0], [%1], 16, %2;"
                 :: "r"(dst), "l"(src), "r"(srcsize) : "memory");
}
#define CP_COMMIT() asm volatile("cp.async.commit_group;" ::: "memory")
#define CP_WAIT1()  asm volatile("cp.async.wait_group 1;" ::: "memory")

__device__ __forceinline__ float gelu_exact(float x) {
    return 0.5f * x * (1.0f + erff(x * 0.70710678118654752f));
}
__device__ __forceinline__ float silu(float x) { return x / (1.0f + __expf(-x)); }

// store value into hi/lo bf16 planes
__device__ __forceinline__ void store_bf2(__nv_bfloat16* base, long long plane,
                                          long long idx, float v) {
    __nv_bfloat16 h = __float2bfloat16(v);
    base[idx] = h;
    base[plane + idx] = __float2bfloat16(v - __bfloat162float(h));
}

__device__ __forceinline__ float block_reduce_sum_256(float v, float* sbuf) {
    int lane = threadIdx.x & 31, w = threadIdx.x >> 5;
    #pragma unroll
    for (int o = 16; o; o >>= 1) v += __shfl_down_sync(0xffffffffu, v, o);
    if (lane == 0) sbuf[w] = v;
    __syncthreads();
    float r = (threadIdx.x < 8) ? sbuf[threadIdx.x] : 0.0f;
    if (w == 0) {
        #pragma unroll
        for (int o = 4; o; o >>= 1) r += __shfl_down_sync(0xffu, r, o);
        if (lane == 0) sbuf[0] = r;
    }
    __syncthreads();
    float out = sbuf[0];
    __syncthreads();
    return out;
}

// ---------------------------------------------------------------------------
// bf16x3 mma.sync GEMM, cp.async 3-stage pipeline.
//   C[M,N] = A[M,K] * W[N,K]^T ; A/W pre-split bf16 hi/lo planes.
//   smem/stage: 4 planes (Ahi,Alo,Bhi,Blo) x 128 rows x 64B, chunk-XOR swizzle.
//   epi: 0 none, 1 +bias, 2 gelu(+bias), 3 +bias+resid, 4 softplus(+bias)
// ---------------------------------------------------------------------------
#define KC      32
#define NSTAGE  3
#define STB     32768
#define TCG_SMEM_BYTES (NSTAGE * STB)

__device__ __forceinline__ void issue_stage(
    uint32_t sbase, int s,
    const __nv_bfloat16* __restrict__ A, long long aplane, int lda,
    const __nv_bfloat16* __restrict__ W, long long wplane,
    int m0, int n0, int N, int K, int arev, int kidx, int tid)
{
    const int k0 = kidx * KC;
    const uint32_t st = sbase + (uint32_t)s * STB;
    #pragma unroll
    for (int it = 0; it < 8; it++) {
        int task = tid + it * 256;
        int plane = task >> 9;
        int rem = task & 511;
        int row = rem >> 2;
        int ch = rem & 3;
        int phys = ch ^ ((row >> 1) & 3);
        uint32_t sdst = st + (uint32_t)plane * 8192u + (uint32_t)(row * 64 + phys * 16);
        const __nv_bfloat16* src;
        int size = 16;
        if (plane < 2) {
            int gm = m0 + row;
            if (arev) gm = (gm & ~(Lk - 1)) + (Lk - 1 - (gm & (Lk - 1)));
            src = A + (plane ? aplane : 0) + (long long)gm * lda + k0 + ch * 8;
        } else {
            int gn = n0 + row;
            if (gn >= N) { gn = N - 1; size = 0; }
            src = W + (plane == 3 ? wplane : 0) + (long long)gn * K + k0 + ch * 8;
        }
        cp_async16(sdst, src, size);
    }
}

__device__ __forceinline__ void mma_tile(float acc[4][4][4],
                                         uint32_t a[4][4], uint32_t b[2][4]) {
    #pragma unroll
    for (int mt = 0; mt < 4; mt++)
        #pragma unroll
        for (int nt = 0; nt < 4; nt++)
            mma_bf16(acc[mt][nt], a[mt], b[nt >> 1][nt & 1], b[nt >> 1][2 + (nt & 1)]);
}

__global__ __launch_bounds__(256, 2)
void tc_gemm(const __nv_bfloat16* __restrict__ A, long long aplane, int lda,
             const __nv_bfloat16* __restrict__ W, long long wplane,
             const float* __restrict__ bias, const float* __restrict__ resid,
             float* __restrict__ C, __nv_bfloat16* __restrict__ Cb, long long cplane,
             int M, int N, int K, int ldc, int arev, int crev, int epi)
{
    extern __shared__ char smem[];
    const uint32_t sbase = smem_to_u32(smem);
    const int tid = threadIdx.x, lane = tid & 31, wid = tid >> 5;
    const int m0 = blockIdx.y * 128, n0 = blockIdx.x * 128;
    const int warpM = (wid & 1) * 64, warpN = (wid >> 1) * 32;
    const uint32_t rsel = (uint32_t)(lane & 15);
    const uint32_t ksel = (uint32_t)(lane >> 4);

    uint32_t aoff[4], asw[4], boff[2], bsw[2];
    #pragma unroll
    for (int mt = 0; mt < 4; mt++) {
        uint32_t r = (uint32_t)warpM + mt * 16u + rsel;
        aoff[mt] = r * 64u; asw[mt] = (r >> 1) & 3u;
    }
    #pragma unroll
    for (int p = 0; p < 2; p++) {
        uint32_t r = (uint32_t)warpN + p * 16u + rsel;
        boff[p] = r * 64u; bsw[p] = (r >> 1) & 3u;
    }

    float acc[4][4][4];
    #pragma unroll
    for (int i = 0; i < 4; i++)
        #pragma unroll
        for (int j = 0; j < 4; j++)
            #pragma unroll
            for (int r = 0; r < 4; r++) acc[i][j][r] = 0.0f;

    const int nch = K / KC;
    #pragma unroll
    for (int s = 0; s < NSTAGE - 1; s++) {
        if (s < nch) issue_stage(sbase, s, A, aplane, lda, W, wplane, m0, n0, N, K, arev, s, tid);
        CP_COMMIT();
    }

    for (int c = 0; c < nch; c++) {
        CP_WAIT1();
        __syncthreads();
        int nxt = c + NSTAGE - 1;
        if (nxt < nch)
            issue_stage(sbase, nxt % NSTAGE, A, aplane, lda, W, wplane, m0, n0, N, K, arev, nxt, tid);
        CP_COMMIT();

        const uint32_t st = sbase + (uint32_t)(c % NSTAGE) * STB;
        #pragma unroll
        for (int ks = 0; ks < 2; ks++) {
            const uint32_t chunk = (uint32_t)(ks * 2) + ksel;
            uint32_t a[4][4], b[2][4];
            #pragma unroll
            for (int mt = 0; mt < 4; mt++)                 // A hi
                ldsm4(a[mt], st + aoff[mt] + (((chunk ^ asw[mt]) << 4)));
            #pragma unroll
            for (int p = 0; p < 2; p++)                    // B hi
                ldsm4(b[p], st + 16384u + boff[p] + (((chunk ^ bsw[p]) << 4)));
            mma_tile(acc, a, b);
            #pragma unroll
            for (int p = 0; p < 2; p++)                    // B lo
                ldsm4(b[p], st + 24576u + boff[p] + (((chunk ^ bsw[p]) << 4)));
            mma_tile(acc, a, b);
            #pragma unroll
            for (int mt = 0; mt < 4; mt++)                 // A lo
                ldsm4(a[mt], st + 8192u + aoff[mt] + (((chunk ^ asw[mt]) << 4)));
            #pragma unroll
            for (int p = 0; p < 2; p++)                    // B hi (again)
                ldsm4(b[p], st + 16384u + boff[p] + (((chunk ^ bsw[p]) << 4)));
            mma_tile(acc, a, b);
        }
    }

    // ---- epilogue ----
    #pragma unroll
    for (int mt = 0; mt < 4; mt++) {
        int r0 = m0 + warpM + mt * 16 + (lane >> 2);
        #pragma unroll
        for (int half = 0; half < 2; half++) {
            int gm = r0 + half * 8;
            if (crev) gm = (gm & ~(Lk - 1)) + (Lk - 1 - (gm & (Lk - 1)));
            #pragma unroll
            for (int nt = 0; nt < 4; nt++) {
                int col = n0 + warpN + nt * 8 + (lane & 3) * 2;
                if (col >= N) continue;
                float v0 = acc[mt][nt][half * 2 + 0];
                float v1 = acc[mt][nt][half * 2 + 1];
                if (epi >= 1) { v0 += bias[col]; v1 += bias[col + 1]; }
                if (epi == 2) { v0 = gelu_exact(v0); v1 = gelu_exact(v1); }
                else if (epi == 4) {
                    v0 = (v0 > 20.0f) ? v0 : log1pf(__expf(v0));
                    v1 = (v1 > 20.0f) ? v1 : log1pf(__expf(v1));
                } else if (epi == 3) {
                    const float* rp = resid + (long long)gm * ldc + col;
                    v0 += rp[0]; v1 += rp[1];
                }
                long long o = (long long)gm * ldc + col;
                if (C) *reinterpret_cast<float2*>(C + o) = make_float2(v0, v1);
                if (Cb) {
                    __nv_bfloat16 h0 = __float2bfloat16(v0);
                    __nv_bfloat16 h1 = __float2bfloat16(v1);
                    Cb[o] = h0; Cb[o + 1] = h1;
                    Cb[cplane + o]     = __float2bfloat16(v0 - __bfloat162float(h0));
                    Cb[cplane + o + 1] = __float2bfloat16(v1 - __bfloat162float(h1));
                }
            }
        }
    }
}

// ---------------------------------------------------------------------------
// weight fp32 -> bf16 hi/lo planes
// ---------------------------------------------------------------------------
__global__ void cvt_w_kernel(const float* __restrict__ src, __nv_bfloat16* __restrict__ dst, int n)
{
    int i4 = blockIdx.x * blockDim.x + threadIdx.x;
    long long base = (long long)i4 * 4;
    if (base >= n) return;
    float4 v = *reinterpret_cast<const float4*>(src + base);
    store_bf2(dst, n, base + 0, v.x);
    store_bf2(dst, n, base + 1, v.y);
    store_bf2(dst, n, base + 2, v.z);
    store_bf2(dst, n, base + 3, v.w);
}

// ---------------------------------------------------------------------------
// pos features -> bf16 planes
// ---------------------------------------------------------------------------
__global__ void pos_feat_kernel(const float* __restrict__ w1, const float* __restrict__ b1)
{
    const int l = blockIdx.x;
    const int j = threadIdx.x;
    const float PI = 3.14159265358979323846f;
    float yy = ((float)(l >> 5) + 0.5f) / (float)Hh * 2.0f - 1.0f;
    float xx = ((float)(l & 31) + 0.5f) / (float)Ww * 2.0f - 1.0f;
    float p2 = sinf(PI * yy), p3 = cosf(PI * yy);
    float p4 = sinf(PI * xx), p5 = cosf(PI * xx);
    const float* w = w1 + j * 6;
    float a = yy * w[0] + xx * w[1] + p2 * w[2] + p3 * w[3] + p4 * w[4] + p5 * w[5] + b1[j];
    store_bf2(b_posh, (long long)Lk * DIMk, (long long)l * DIMk + j, gelu_exact(a));
}

// ---------------------------------------------------------------------------
// scan_in = LN(tokens) + pos  -> bf16 planes
// ---------------------------------------------------------------------------
__global__ void ln_add_pos_kernel(const float* __restrict__ tokens,
                                  const float* __restrict__ g, const float* __restrict__ b)
{
    __shared__ float sbuf[8];
    const int m = blockIdx.x;
    const int l = m & (Lk - 1);
    const float* x = tokens + (long long)m * DIMk;
    int c0 = threadIdx.x, c1 = threadIdx.x + 256;
    float v0 = x[c0], v1 = x[c1];
    float mu = block_reduce_sum_256(v0 + v1, sbuf) * (1.0f / DIMk);
    float d0 = v0 - mu, d1 = v1 - mu;
    float var = block_reduce_sum_256(d0 * d0 + d1 * d1, sbuf) * (1.0f / DIMk);
    float inv = rsqrtf(var + 1e-5f);
    const long long n = (long long)Mrows * DIMk;
    store_bf2(b_scanin, n, (long long)m * DIMk + c0, d0 * inv * g[c0] + b[c0] + g_pos[l * DIMk + c0]);
    store_bf2(b_scanin, n, (long long)m * DIMk + c1, d1 * inv * g[c1] + b[c1] + g_pos[l * DIMk + c1]);
}

// ---------------------------------------------------------------------------
// causal depthwise conv + silu -> fp32 xc (scan) + bf16 planes (x_proj)
// ---------------------------------------------------------------------------
__global__ void conv_kernel(const float* __restrict__ cw, const float* __restrict__ cb)
{
    long long idx = (long long)blockIdx.x * blockDim.x + threadIdx.x;
    if (idx >= 2ll * Mrows * DIk) return;
    int d   = (int)(idx & (DIk - 1));
    long long m = idx >> 10;
    int dir = (int)(m >> 13);
    int bl  = (int)(m & (Mrows - 1));
    int l   = bl & (Lk - 1);
    const float* xin = g_xz + (long long)dir * Mrows * (2 * DIk);
    long long rowbase = (long long)bl * (2 * DIk) + d;
    const float* w = cw + ((long long)dir * DIk + d) * DCONVk;
    float acc = cb[dir * DIk + d];
    #pragma unroll
    for (int k = 0; k < DCONVk; k++) {
        int src = l - (DCONVk - 1) + k;
        if (src >= 0) acc += xin[rowbase + (long long)(src - l) * (2 * DIk)] * w[k];
    }
    float v = silu(acc);
    g_xc[idx] = v;
    store_bf2(b_xc, 2ll * Mrows * DIk, idx, v);
}

// ---------------------------------------------------------------------------
// selective scan -> bf16 ybuf planes
// ---------------------------------------------------------------------------
__global__ __launch_bounds__(128, 8)
void scan_kernel(const float* __restrict__ A_log, const float* __restrict__ Dp)
{
    const int blk = blockIdx.x;
    const int dir = blk >> 6;
    const int b   = (blk >> 3) & 7;
    const int d   = ((blk & 7) << 7) + threadIdx.x;
    const int lane = threadIdx.x & 31;

    const long long base = ((long long)dir * Mrows + (long long)b * Lk);
    const float* dl  = g_delta + base * DIk + d;
    const float* xcd = g_xc    + base * DIk + d;
    const float* pj  = g_proj  + base * 64 + DTRk + lane;
    const float* zz  = g_xz    + base * (2 * DIk) + DIk + d;
    const long long ybase = base * DIk + d;
    const long long yplane = 2ll * Mrows * DIk;

    float A[DSk];
    bool fast = true;
    #pragma unroll
    for (int s = 0; s < DSk; s++) {
        A[s] = -expf(A_log[((long long)dir * DIk + d) * DSk + s]);
        float t = (float)(s + 1);
        if (fabsf(A[s] + t) > 1e-4f * t) fast = false;
    }
    const float Dv = Dp[dir * DIk + d];
    float h[DSk];
    #pragma unroll
    for (int s = 0; s < DSk; s++) h[s] = 0.0f;

    float rdt[4], rxt[4], rzt[4], rbc[4];
    #pragma unroll
    for (int j = 0; j < 4; j++) {
        rdt[j] = dl[(long long)j * DIk];
        rxt[j] = xcd[(long long)j * DIk];
        rzt[j] = zz[(long long)j * (2 * DIk)];
        rbc[j] = pj[(long long)j * 64];
    }

    for (int t = 0; t < Lk; t += 4) {
        #pragma unroll
        for (int j = 0; j < 4; j++) {
            float dt = rdt[j], xt = rxt[j], zt = rzt[j], bcv = rbc[j];
            int tn = t + j + 4;
            if (tn < Lk) {
                rdt[j] = dl[(long long)tn * DIk];
                rxt[j] = xcd[(long long)tn * DIk];
                rzt[j] = zz[(long long)tn * (2 * DIk)];
                rbc[j] = pj[(long long)tn * 64];
            }
            float dx = dt * xt;
            float y = 0.0f;
            if (fast) {
                float e1 = __expf(-dt);
                float w = e1;
                #pragma unroll
                for (int s = 0; s < DSk; s++) {
                    float Bs = __shfl_sync(0xffffffffu, bcv, s);
                    float Cs = __shfl_sync(0xffffffffu, bcv, 16 + s);
                    h[s] = h[s] * w + dx * Bs;
                    y = fmaf(h[s], Cs, y);
                    w *= e1;
                }
            } else {
                #pragma unroll
                for (int s = 0; s < DSk; s++) {
                    float Bs = __shfl_sync(0xffffffffu, bcv, s);
                    float Cs = __shfl_sync(0xffffffffu, bcv, 16 + s);
                    h[s] = h[s] * __expf(dt * A[s]) + dx * Bs;
                    y = fmaf(h[s], Cs, y);
                }
            }
            store_bf2(b_ybuf, yplane, ybase + (long long)(t + j) * DIk,
                      (y + xt * Dv) * silu(zt));
        }
    }
}

// ---------------------------------------------------------------------------
// broadcast pos into b_cat[:, 1024:1536] planes
// ---------------------------------------------------------------------------
__global__ void posbc_kernel()
{
    long long idx = (long long)blockIdx.x * blockDim.x + threadIdx.x;
    int c = (int)(idx & (DIMk - 1));
    int m = (int)(idx >> 9);
    int l = m & (Lk - 1);
    store_bf2(b_cat, (long long)Mrows * 3 * DIMk,
              (long long)m * (3 * DIMk) + 2 * DIMk + c, g_pos[l * DIMk + c]);
}

// ---------------------------------------------------------------------------
// delta_ln = LN(mix, dn) -> fp32 dln (resid);  x2 = LN(delta_ln, fn) -> bf16
// ---------------------------------------------------------------------------
__global__ void double_ln_kernel(const float* __restrict__ dng, const float* __restrict__ dnb,
                                 const float* __restrict__ fng, const float* __restrict__ fnb)
{
    __shared__ float sbuf[8];
    const int m = blockIdx.x;
    const float* x = g_mix + (long long)m * DIMk;
    int c0 = threadIdx.x, c1 = threadIdx.x + 256;
    float v0 = x[c0], v1 = x[c1];
    float mu = block_reduce_sum_256(v0 + v1, sbuf) * (1.0f / DIMk);
    float d0 = v0 - mu, d1 = v1 - mu;
    float var = block_reduce_sum_256(d0 * d0 + d1 * d1, sbuf) * (1.0f / DIMk);
    float inv = rsqrtf(var + 1e-5f);
    float e0 = d0 * inv * dng[c0] + dnb[c0];
    float e1 = d1 * inv * dng[c1] + dnb[c1];
    g_dln[(long long)m * DIMk + c0] = e0;
    g_dln[(long long)m * DIMk + c1] = e1;
    float mu2 = block_reduce_sum_256(e0 + e1, sbuf) * (1.0f / DIMk);
    float f0 = e0 - mu2, f1 = e1 - mu2;
    float var2 = block_reduce_sum_256(f0 * f0 + f1 * f1, sbuf) * (1.0f / DIMk);
    float inv2 = rsqrtf(var2 + 1e-5f);
    const long long n = (long long)Mrows * DIMk;
    store_bf2(b_x2, n, (long long)m * DIMk + c0, f0 * inv2 * fng[c0] + fnb[c0]);
    store_bf2(b_x2, n, (long long)m * DIMk + c1, f1 * inv2 * fng[c1] + fnb[c1]);
}

// ---------------------------------------------------------------------------
// launch
// ---------------------------------------------------------------------------
extern "C" void kernel_launch(void* const* d_in, const int* in_sizes, int n_in,
                              void* d_out, int out_size)
{
    const float* tokens   = (const float*)d_in[0];
    const float* in_g     = (const float*)d_in[3];
    const float* in_b     = (const float*)d_in[4];
    const float* pos_w1   = (const float*)d_in[5];
    const float* pos_b1   = (const float*)d_in[6];
    const float* pos_w2   = (const float*)d_in[7];
    const float* pos_b2   = (const float*)d_in[8];
    const float* m_in_w   = (const float*)d_in[9];
    const float* m_conv_w = (const float*)d_in[10];
    const float* m_conv_b = (const float*)d_in[11];
    const float* m_xproj_w= (const float*)d_in[12];
    const float* m_dt_w   = (const float*)d_in[13];
    const float* m_dt_b   = (const float*)d_in[14];
    const float* m_A_log  = (const float*)d_in[15];
    const float* m_D      = (const float*)d_in[16];
    const float* m_out_w  = (const float*)d_in[17];
    const float* mix_w    = (const float*)d_in[18];
    const float* mix_b    = (const float*)d_in[19];
    const float* dn_g     = (const float*)d_in[20];
    const float* dn_b     = (const float*)d_in[21];
    const float* fn_g     = (const float*)d_in[22];
    const float* fn_b     = (const float*)d_in[23];
    const float* ffn_w1   = (const float*)d_in[24];
    const float* ffn_b1   = (const float*)d_in[25];
    const float* ffn_w2   = (const float*)d_in[26];
    const float* ffn_b2   = (const float*)d_in[27];
    float* out = (float*)d_out;

    float *p_pos, *p_xz, *p_xc, *p_proj, *p_delta, *p_mix, *p_dln;
    cudaGetSymbolAddress((void**)&p_pos,   g_pos);
    cudaGetSymbolAddress((void**)&p_xz,    g_xz);
    cudaGetSymbolAddress((void**)&p_xc,    g_xc);
    cudaGetSymbolAddress((void**)&p_proj,  g_proj);
    cudaGetSymbolAddress((void**)&p_delta, g_delta);
    cudaGetSymbolAddress((void**)&p_mix,   g_mix);
    cudaGetSymbolAddress((void**)&p_dln,   g_dln);

    __nv_bfloat16 *q_posh, *q_scanin, *q_xc, *q_proj, *q_ybuf, *q_cat, *q_x2, *q_hbuf,
                  *q_posw2, *q_inw, *q_xprojw, *q_dtw, *q_outw, *q_mixw, *q_ffn1w, *q_ffn2w;
    cudaGetSymbolAddress((void**)&q_posh,   b_posh);
    cudaGetSymbolAddress((void**)&q_scanin, b_scanin);
    cudaGetSymbolAddress((void**)&q_xc,     b_xc);
    cudaGetSymbolAddress((void**)&q_proj,   b_proj);
    cudaGetSymbolAddress((void**)&q_ybuf,   b_ybuf);
    cudaGetSymbolAddress((void**)&q_cat,    b_cat);
    cudaGetSymbolAddress((void**)&q_x2,     b_x2);
    cudaGetSymbolAddress((void**)&q_hbuf,   b_hbuf);
    cudaGetSymbolAddress((void**)&q_posw2,  b_posw2);
    cudaGetSymbolAddress((void**)&q_inw,    b_inw);
    cudaGetSymbolAddress((void**)&q_xprojw, b_xprojw);
    cudaGetSymbolAddress((void**)&q_dtw,    b_dtw);
    cudaGetSymbolAddress((void**)&q_outw,   b_outw);
    cudaGetSymbolAddress((void**)&q_mixw,   b_mixw);
    cudaGetSymbolAddress((void**)&q_ffn1w,  b_ffn1w);
    cudaGetSymbolAddress((void**)&q_ffn2w,  b_ffn2w);

    static int smem_set = 0;
    if (!smem_set) {
        cudaFuncSetAttribute(tc_gemm, cudaFuncAttributeMaxDynamicSharedMemorySize, TCG_SMEM_BYTES);
        smem_set = 1;
    }
    const int SB = TCG_SMEM_BYTES;

    // 0) weight conversions (bandwidth-trivial)
    auto cvt = [](const float* s, __nv_bfloat16* d, int n) {
        cvt_w_kernel<<<(n / 4 + 255) / 256, 256>>>(s, d, n);
    };
    cvt(pos_w2,    q_posw2,  DIMk * DIMk);
    cvt(m_in_w,    q_inw,    2 * (2 * DIk) * DIMk);
    cvt(m_xproj_w, q_xprojw, 2 * 64 * DIk);
    cvt(m_dt_w,    q_dtw,    2 * DIk * DTRk);
    cvt(m_out_w,   q_outw,   2 * DIMk * DIk);
    cvt(mix_w,     q_mixw,   DIMk * 3 * DIMk);
    cvt(ffn_w1,    q_ffn1w,  HIDk * DIMk);
    cvt(ffn_w2,    q_ffn2w,  DIMk * HIDk);

    // 1) pos MLP
    pos_feat_kernel<<<Lk, DIMk>>>(pos_w1, pos_b1);
    tc_gemm<<<dim3(4, 8), 256, SB>>>(q_posh, (long long)Lk * DIMk, DIMk,
                                     q_posw2, (long long)DIMk * DIMk,
                                     pos_b2, nullptr, p_pos, nullptr, 0,
                                     Lk, DIMk, DIMk, DIMk, 0, 0, 1);
    // 2) scan_in = LN(tokens)+pos
    ln_add_pos_kernel<<<Mrows, 256>>>(tokens, in_g, in_b);

    // 3) in_proj (dir1 reads rows reversed)
    for (int dir = 0; dir < 2; dir++) {
        tc_gemm<<<dim3(16, 64), 256, SB>>>(
            q_scanin, (long long)Mrows * DIMk, DIMk,
            q_inw + (long long)dir * (2 * DIk) * DIMk, 2ll * (2 * DIk) * DIMk,
            nullptr, nullptr,
            p_xz + (long long)dir * Mrows * (2 * DIk), nullptr, 0,
            Mrows, 2 * DIk, DIMk, 2 * DIk, dir, 0, 0);
    }
    // 4) conv + silu
    conv_kernel<<<(unsigned)((2ll * Mrows * DIk + 255) / 256), 256>>>(m_conv_w, m_conv_b);

    // 5) x_proj (N=64) ; 6) dt proj + softplus (K=32, lda=64)
    for (int dir = 0; dir < 2; dir++) {
        tc_gemm<<<dim3(1, 64), 256, SB>>>(
            q_xc + (long long)dir * Mrows * DIk, 2ll * Mrows * DIk, DIk,
            q_xprojw + (long long)dir * 64 * DIk, 2ll * 64 * DIk,
            nullptr, nullptr,
            p_proj + (long long)dir * Mrows * 64,
            q_proj + (long long)dir * Mrows * 64, 2ll * Mrows * 64,
            Mrows, 64, DIk, 64, 0, 0, 0);
        tc_gemm<<<dim3(8, 64), 256, SB>>>(
            q_proj + (long long)dir * Mrows * 64, 2ll * Mrows * 64, 64,
            q_dtw + (long long)dir * DIk * DTRk, 2ll * DIk * DTRk,
            m_dt_b + dir * DIk, nullptr,
            p_delta + (long long)dir * Mrows * DIk, nullptr, 0,
            Mrows, DIk, DTRk, DIk, 0, 0, 4);
    }
    // 7) selective scan + gating -> bf16 ybuf
    scan_kernel<<<128, 128>>>(m_A_log, m_D);

    // 8) out_proj -> bf16 cat slices (bwd un-reversed on store)
    for (int dir = 0; dir < 2; dir++) {
        tc_gemm<<<dim3(4, 64), 256, SB>>>(
            q_ybuf + (long long)dir * Mrows * DIk, 2ll * Mrows * DIk, DIk,
            q_outw + (long long)dir * DIMk * DIk, 2ll * DIMk * DIk,
            nullptr, nullptr,
            nullptr, q_cat + dir * DIMk, (long long)Mrows * 3 * DIMk,
            Mrows, DIMk, DIk, 3 * DIMk, 0, dir, 0);
    }
    // 9) pos broadcast into cat third slice
    posbc_kernel<<<(unsigned)(((long long)Mrows * DIMk + 255) / 256), 256>>>();

    // 10) mix GEMM
    tc_gemm<<<dim3(4, 64), 256, SB>>>(
        q_cat, (long long)Mrows * 3 * DIMk, 3 * DIMk,
        q_mixw, (long long)DIMk * 3 * DIMk,
        mix_b, nullptr, p_mix, nullptr, 0,
        Mrows, DIMk, 3 * DIMk, DIMk, 0, 0, 1);
    // 11) double LN
    double_ln_kernel<<<Mrows, 256>>>(dn_g, dn_b, fn_g, fn_b);

    // 12) FFN
    tc_gemm<<<dim3(8, 64), 256, SB>>>(
        q_x2, (long long)Mrows * DIMk, DIMk,
        q_ffn1w, (long long)HIDk * DIMk,
        ffn_b1, nullptr, nullptr, q_hbuf, (long long)Mrows * HIDk,
        Mrows, HIDk, DIMk, HIDk, 0, 0, 2);
    tc_gemm<<<dim3(4, 64), 256, SB>>>(
        q_hbuf, (long long)Mrows * HIDk, HIDk,
        q_ffn2w, (long long)DIMk * HIDk,
        ffn_b2, p_dln, out, nullptr, 0,
        Mrows, DIMk, HIDk, DIMk, 0, 0, 3);
    (void)in_sizes; (void)n_in; (void)out_size;
}

// round 13
// speedup vs baseline: 1.8808x; 1.0352x over previous
#include <cuda_runtime.h>
#include <cuda_bf16.h>
#include <math.h>
#include <stdint.h>

// ---------------------------------------------------------------------------
// Problem constants
// ---------------------------------------------------------------------------
#define Bk     8
#define Hh     32
#define Ww     32
#define Lk     1024
#define DIMk   512
#define DSk    16
#define DCONVk 4
#define DIk    1024
#define DTRk   32
#define HIDk   1024
#define Mrows  (Bk*Lk)          // 8192

// ---------------------------------------------------------------------------
// fp32 scratch
// ---------------------------------------------------------------------------
__device__ float g_pos[Lk * DIMk];
__device__ float g_xz[(long long)Mrows * 4096];   // [8192][4096]: dir*2048 + (xin|z)
__device__ float g_proj[2ll * Mrows * 64];
__device__ float g_delta[2ll * Mrows * DIk];
__device__ float g_mix[Mrows * DIMk];
__device__ float g_dln[Mrows * DIMk];

// ---------------------------------------------------------------------------
// bf16 hi/lo split buffers: [hi plane (n elems) | lo plane (n elems)]
// ---------------------------------------------------------------------------
__device__ __nv_bfloat16 b_posh  [2ll * Lk * DIMk];
__device__ __nv_bfloat16 b_scanin[2ll * Mrows * DIMk];
__device__ __nv_bfloat16 b_xc    [2ll * 2 * Mrows * DIk];
__device__ __nv_bfloat16 b_proj  [2ll * 2 * Mrows * 64];
__device__ __nv_bfloat16 b_ybuf  [2ll * 2 * Mrows * DIk];
__device__ __nv_bfloat16 b_cat   [2ll * Mrows * 3 * DIMk];
__device__ __nv_bfloat16 b_x2    [2ll * Mrows * DIMk];
__device__ __nv_bfloat16 b_hbuf  [2ll * Mrows * HIDk];
// weights
__device__ __nv_bfloat16 b_posw2 [2ll * DIMk * DIMk];
__device__ __nv_bfloat16 b_inw   [2ll * 4096 * DIMk];       // both dirs concatenated
__device__ __nv_bfloat16 b_xprojw[2ll * 2 * 64 * DIk];
__device__ __nv_bfloat16 b_dtw   [2ll * 2 * DIk * DTRk];
__device__ __nv_bfloat16 b_outw  [2ll * 2 * DIMk * DIk];
__device__ __nv_bfloat16 b_mixw  [2ll * DIMk * 3 * DIMk];
__device__ __nv_bfloat16 b_ffn1w [2ll * HIDk * DIMk];
__device__ __nv_bfloat16 b_ffn2w [2ll * DIMk * HIDk];

// ---------------------------------------------------------------------------
// Helpers (sm_80-era PTX only)
// ---------------------------------------------------------------------------
__device__ __forceinline__ uint32_t smem_to_u32(const void* p) {
    uint32_t a;
    asm("{ .reg .u64 t; cvta.to.shared.u64 t, %1; cvt.u32.u64 %0, t; }" : "=r"(a) : "l"(p));
    return a;
}
__device__ __forceinline__ void ldsm4(uint32_t* r, uint32_t addr) {
    asm volatile("ldmatrix.sync.aligned.m8n8.x4.shared.b16 {%0,%1,%2,%3}, [%4];"
                 : "=r"(r[0]), "=r"(r[1]), "=r"(r[2]), "=r"(r[3]) : "r"(addr));
}
__device__ __forceinline__ void mma_bf16(float* c, const uint32_t* a, uint32_t b0, uint32_t b1) {
    asm volatile("mma.sync.aligned.m16n8k16.row.col.f32.bf16.bf16.f32 "
                 "{%0,%1,%2,%3}, {%4,%5,%6,%7}, {%8,%9}, {%0,%1,%2,%3};"
                 : "+f"(c[0]), "+f"(c[1]), "+f"(c[2]), "+f"(c[3])
                 : "r"(a[0]), "r"(a[1]), "r"(a[2]), "r"(a[3]), "r"(b0), "r"(b1));
}
__device__ __forceinline__ void cp_async16(uint32_t dst, const void* src, int srcsize) {
    asm volatile("cp.async.ca.shared.global [%0], [%1], 16, %2;"
                 :: "r"(dst), "l"(src), "r"(srcsize) : "memory");
}
#define CP_COMMIT() asm volatile("cp.async.commit_group;" ::: "memory")
#define CP_WAIT1()  asm volatile("cp.async.wait_group 1;" ::: "memory")

__device__ __forceinline__ float gelu_exact(float x) {
    return 0.5f * x * (1.0f + erff(x * 0.70710678118654752f));
}
__device__ __forceinline__ float silu(float x) { return x / (1.0f + __expf(-x)); }

__device__ __forceinline__ void store_bf2(__nv_bfloat16* base, long long plane,
                                          long long idx, float v) {
    __nv_bfloat16 h = __float2bfloat16(v);
    base[idx] = h;
    base[plane + idx] = __float2bfloat16(v - __bfloat162float(h));
}

__device__ __forceinline__ float block_reduce_sum_256(float v, float* sbuf) {
    int lane = threadIdx.x & 31, w = threadIdx.x >> 5;
    #pragma unroll
    for (int o = 16; o; o >>= 1) v += __shfl_down_sync(0xffffffffu, v, o);
    if (lane == 0) sbuf[w] = v;
    __syncthreads();
    float r = (threadIdx.x < 8) ? sbuf[threadIdx.x] : 0.0f;
    if (w == 0) {
        #pragma unroll
        for (int o = 4; o; o >>= 1) r += __shfl_down_sync(0xffu, r, o);
        if (lane == 0) sbuf[0] = r;
    }
    __syncthreads();
    float out = sbuf[0];
    __syncthreads();
    return out;
}

// ---------------------------------------------------------------------------
// Fused weight conversion: all 8 weight tensors in one launch.
// ---------------------------------------------------------------------------
#define WS0 (DIMk*DIMk)            // posw2   262144
#define WS1 (4096*DIMk)            // inw    2097152
#define WS2 (2*64*DIk)             // xprojw  131072
#define WS3 (2*DIk*DTRk)           // dtw      65536
#define WS4 (2*DIMk*DIk)           // outw   1048576
#define WS5 (DIMk*3*DIMk)          // mixw    786432
#define WS6 (HIDk*DIMk)            // ffn1w   524288
#define WS7 (DIMk*HIDk)            // ffn2w   524288
#define WP1 (WS0)
#define WP2 (WP1+WS1)
#define WP3 (WP2+WS2)
#define WP4 (WP3+WS3)
#define WP5 (WP4+WS4)
#define WP6 (WP5+WS5)
#define WP7 (WP6+WS6)
#define WTOT (WP7+WS7)             // 5439488 floats

__global__ void cvt_all_kernel(const float* __restrict__ s0, const float* __restrict__ s1,
                               const float* __restrict__ s2, const float* __restrict__ s3,
                               const float* __restrict__ s4, const float* __restrict__ s5,
                               const float* __restrict__ s6, const float* __restrict__ s7)
{
    long long base = ((long long)blockIdx.x * blockDim.x + threadIdx.x) * 4;
    if (base >= WTOT) return;
    const float* src; __nv_bfloat16* dst; long long off; long long n;
    if      (base < WP1) { src = s0; dst = b_posw2;  off = base;       n = WS0; }
    else if (base < WP2) { src = s1; dst = b_inw;    off = base - WP1; n = WS1; }
    else if (base < WP3) { src = s2; dst = b_xprojw; off = base - WP2; n = WS2; }
    else if (base < WP4) { src = s3; dst = b_dtw;    off = base - WP3; n = WS3; }
    else if (base < WP5) { src = s4; dst = b_outw;   off = base - WP4; n = WS4; }
    else if (base < WP6) { src = s5; dst = b_mixw;   off = base - WP5; n = WS5; }
    else if (base < WP7) { src = s6; dst = b_ffn1w;  off = base - WP6; n = WS6; }
    else                 { src = s7; dst = b_ffn2w;  off = base - WP7; n = WS7; }
    float4 v = *reinterpret_cast<const float4*>(src + off);
    store_bf2(dst, n, off + 0, v.x);
    store_bf2(dst, n, off + 1, v.y);
    store_bf2(dst, n, off + 2, v.z);
    store_bf2(dst, n, off + 3, v.w);
}

// ---------------------------------------------------------------------------
// bf16x3 mma.sync GEMM, cp.async 3-stage pipeline, 12-ldsm inner loop.
// ---------------------------------------------------------------------------
#define KC      32
#define NSTAGE  3
#define STB     32768
#define TCG_SMEM_BYTES (NSTAGE * STB)

__device__ __forceinline__ void issue_stage(
    uint32_t sbase, int s,
    const __nv_bfloat16* __restrict__ A, long long aplane, int lda,
    const __nv_bfloat16* __restrict__ W, long long wplane,
    int m0, int n0, int N, int K, int kidx, int tid)
{
    const int k0 = kidx * KC;
    const uint32_t st = sbase + (uint32_t)s * STB;
    #pragma unroll
    for (int it = 0; it < 8; it++) {
        int task = tid + it * 256;
        int plane = task >> 9;
        int rem = task & 511;
        int row = rem >> 2;
        int ch = rem & 3;
        int phys = ch ^ ((row >> 1) & 3);
        uint32_t sdst = st + (uint32_t)plane * 8192u + (uint32_t)(row * 64 + phys * 16);
        const __nv_bfloat16* src;
        int size = 16;
        if (plane < 2) {
            int gm = m0 + row;
            src = A + (plane ? aplane : 0) + (long long)gm * lda + k0 + ch * 8;
        } else {
            int gn = n0 + row;
            if (gn >= N) { gn = N - 1; size = 0; }
            src = W + (plane == 3 ? wplane : 0) + (long long)gn * K + k0 + ch * 8;
        }
        cp_async16(sdst, src, size);
    }
}

__device__ __forceinline__ void mma_tile(float acc[4][4][4],
                                         uint32_t a[4][4], uint32_t b[2][4]) {
    #pragma unroll
    for (int mt = 0; mt < 4; mt++)
        #pragma unroll
        for (int nt = 0; nt < 4; nt++)
            mma_bf16(acc[mt][nt], a[mt], b[nt >> 1][nt & 1], b[nt >> 1][2 + (nt & 1)]);
}

__global__ __launch_bounds__(256, 2)
void tc_gemm(const __nv_bfloat16* __restrict__ A, long long aplane, int lda,
             const __nv_bfloat16* __restrict__ W, long long wplane,
             const float* __restrict__ bias, const float* __restrict__ resid,
             float* __restrict__ C, __nv_bfloat16* __restrict__ Cb, long long cplane,
             int M, int N, int K, int ldc, int crev, int epi)
{
    extern __shared__ char smem[];
    const uint32_t sbase = smem_to_u32(smem);
    const int tid = threadIdx.x, lane = tid & 31, wid = tid >> 5;
    const int m0 = blockIdx.y * 128, n0 = blockIdx.x * 128;
    const int warpM = (wid & 1) * 64, warpN = (wid >> 1) * 32;
    const uint32_t rsel = (uint32_t)(lane & 15);
    const uint32_t ksel = (uint32_t)(lane >> 4);

    uint32_t aoff[4], asw[4], boff[2], bsw[2];
    #pragma unroll
    for (int mt = 0; mt < 4; mt++) {
        uint32_t r = (uint32_t)warpM + mt * 16u + rsel;
        aoff[mt] = r * 64u; asw[mt] = (r >> 1) & 3u;
    }
    #pragma unroll
    for (int p = 0; p < 2; p++) {
        uint32_t r = (uint32_t)warpN + p * 16u + rsel;
        boff[p] = r * 64u; bsw[p] = (r >> 1) & 3u;
    }

    float acc[4][4][4];
    #pragma unroll
    for (int i = 0; i < 4; i++)
        #pragma unroll
        for (int j = 0; j < 4; j++)
            #pragma unroll
            for (int r = 0; r < 4; r++) acc[i][j][r] = 0.0f;

    const int nch = K / KC;
    #pragma unroll
    for (int s = 0; s < NSTAGE - 1; s++) {
        if (s < nch) issue_stage(sbase, s, A, aplane, lda, W, wplane, m0, n0, N, K, s, tid);
        CP_COMMIT();
    }

    for (int c = 0; c < nch; c++) {
        CP_WAIT1();
        __syncthreads();
        int nxt = c + NSTAGE - 1;
        if (nxt < nch)
            issue_stage(sbase, nxt % NSTAGE, A, aplane, lda, W, wplane, m0, n0, N, K, nxt, tid);
        CP_COMMIT();

        const uint32_t st = sbase + (uint32_t)(c % NSTAGE) * STB;
        #pragma unroll
        for (int ks = 0; ks < 2; ks++) {
            const uint32_t chunk = (uint32_t)(ks * 2) + ksel;
            uint32_t a[4][4], bhi[2][4], blo[2][4];
            #pragma unroll
            for (int mt = 0; mt < 4; mt++)                 // A hi
                ldsm4(a[mt], st + aoff[mt] + (((chunk ^ asw[mt]) << 4)));
            #pragma unroll
            for (int p = 0; p < 2; p++)                    // B hi
                ldsm4(bhi[p], st + 16384u + boff[p] + (((chunk ^ bsw[p]) << 4)));
            #pragma unroll
            for (int p = 0; p < 2; p++)                    // B lo
                ldsm4(blo[p], st + 24576u + boff[p] + (((chunk ^ bsw[p]) << 4)));
            mma_tile(acc, a, bhi);
            mma_tile(acc, a, blo);
            #pragma unroll
            for (int mt = 0; mt < 4; mt++)                 // A lo (reuse regs)
                ldsm4(a[mt], st + 8192u + aoff[mt] + (((chunk ^ asw[mt]) << 4)));
            mma_tile(acc, a, bhi);
        }
    }

    // ---- epilogue ----
    #pragma unroll
    for (int mt = 0; mt < 4; mt++) {
        int r0 = m0 + warpM + mt * 16 + (lane >> 2);
        #pragma unroll
        for (int half = 0; half < 2; half++) {
            int gm = r0 + half * 8;
            if (crev) gm = (gm & ~(Lk - 1)) + (Lk - 1 - (gm & (Lk - 1)));
            #pragma unroll
            for (int nt = 0; nt < 4; nt++) {
                int col = n0 + warpN + nt * 8 + (lane & 3) * 2;
                if (col >= N) continue;
                float v0 = acc[mt][nt][half * 2 + 0];
                float v1 = acc[mt][nt][half * 2 + 1];
                if (epi >= 1) { v0 += bias[col]; v1 += bias[col + 1]; }
                if (epi == 2) { v0 = gelu_exact(v0); v1 = gelu_exact(v1); }
                else if (epi == 4) {
                    v0 = (v0 > 20.0f) ? v0 : log1pf(__expf(v0));
                    v1 = (v1 > 20.0f) ? v1 : log1pf(__expf(v1));
                } else if (epi == 3) {
                    const float* rp = resid + (long long)gm * ldc + col;
                    v0 += rp[0]; v1 += rp[1];
                }
                long long o = (long long)gm * ldc + col;
                if (C) *reinterpret_cast<float2*>(C + o) = make_float2(v0, v1);
                if (Cb) {
                    __nv_bfloat16 h0 = __float2bfloat16(v0);
                    __nv_bfloat16 h1 = __float2bfloat16(v1);
                    Cb[o] = h0; Cb[o + 1] = h1;
                    Cb[cplane + o]     = __float2bfloat16(v0 - __bfloat162float(h0));
                    Cb[cplane + o + 1] = __float2bfloat16(v1 - __bfloat162float(h1));
                }
            }
        }
    }
}

// ---------------------------------------------------------------------------
// pos features -> bf16 planes
// ---------------------------------------------------------------------------
__global__ void pos_feat_kernel(const float* __restrict__ w1, const float* __restrict__ b1)
{
    const int l = blockIdx.x;
    const int j = threadIdx.x;
    const float PI = 3.14159265358979323846f;
    float yy = ((float)(l >> 5) + 0.5f) / (float)Hh * 2.0f - 1.0f;
    float xx = ((float)(l & 31) + 0.5f) / (float)Ww * 2.0f - 1.0f;
    float p2 = sinf(PI * yy), p3 = cosf(PI * yy);
    float p4 = sinf(PI * xx), p5 = cosf(PI * xx);
    const float* w = w1 + j * 6;
    float a = yy * w[0] + xx * w[1] + p2 * w[2] + p3 * w[3] + p4 * w[4] + p5 * w[5] + b1[j];
    store_bf2(b_posh, (long long)Lk * DIMk, (long long)l * DIMk + j, gelu_exact(a));
}

// ---------------------------------------------------------------------------
// scan_in = LN(tokens) + pos  -> bf16 planes
// ---------------------------------------------------------------------------
__global__ void ln_add_pos_kernel(const float* __restrict__ tokens,
                                  const float* __restrict__ g, const float* __restrict__ b)
{
    __shared__ float sbuf[8];
    const int m = blockIdx.x;
    const int l = m & (Lk - 1);
    const float* x = tokens + (long long)m * DIMk;
    int c0 = threadIdx.x, c1 = threadIdx.x + 256;
    float v0 = x[c0], v1 = x[c1];
    float mu = block_reduce_sum_256(v0 + v1, sbuf) * (1.0f / DIMk);
    float d0 = v0 - mu, d1 = v1 - mu;
    float var = block_reduce_sum_256(d0 * d0 + d1 * d1, sbuf) * (1.0f / DIMk);
    float inv = rsqrtf(var + 1e-5f);
    const long long n = (long long)Mrows * DIMk;
    store_bf2(b_scanin, n, (long long)m * DIMk + c0, d0 * inv * g[c0] + b[c0] + g_pos[l * DIMk + c0]);
    store_bf2(b_scanin, n, (long long)m * DIMk + c1, d1 * inv * g[c1] + b[c1] + g_pos[l * DIMk + c1]);
}

// ---------------------------------------------------------------------------
// causal depthwise conv + silu. dir1 reads xin time-reversed from merged g_xz.
// output b_xc stays in per-dir (reversed for dir1) space.
// ---------------------------------------------------------------------------
__global__ void conv_kernel(const float* __restrict__ cw, const float* __restrict__ cb)
{
    long long idx = (long long)blockIdx.x * blockDim.x + threadIdx.x;
    if (idx >= 2ll * Mrows * DIk) return;
    int d   = (int)(idx & (DIk - 1));
    long long m = idx >> 10;
    int dir = (int)(m >> 13);
    int bl  = (int)(m & (Mrows - 1));
    int l   = bl & (Lk - 1);
    int brow = bl & ~(Lk - 1);
    const float* w = cw + ((long long)dir * DIk + d) * DCONVk;
    float acc = cb[dir * DIk + d];
    #pragma unroll
    for (int k = 0; k < DCONVk; k++) {
        int s = l - (DCONVk - 1) + k;
        if (s >= 0) {
            int row = brow + (dir ? (Lk - 1 - s) : s);
            acc += g_xz[(long long)row * 4096 + dir * 2048 + d] * w[k];
        }
    }
    store_bf2(b_xc, 2ll * Mrows * DIk, idx, silu(acc));
}

// ---------------------------------------------------------------------------
// selective scan: shuffle-broadcast B/C, ring-8 prefetch, fast exp path.
// xc reconstructed from bf16 hi+lo planes; z read from merged g_xz
// (dir1 walks rows backwards).
// ---------------------------------------------------------------------------
#define RING 8
__global__ __launch_bounds__(128)
void scan_kernel(const float* __restrict__ A_log, const float* __restrict__ Dp)
{
    const int blk = blockIdx.x;
    const int dir = blk >> 6;
    const int b   = (blk >> 3) & 7;
    const int d   = ((blk & 7) << 7) + threadIdx.x;
    const int lane = threadIdx.x & 31;

    const long long base = ((long long)dir * Mrows + (long long)b * Lk);
    const float* dl  = g_delta + base * DIk + d;
    const __nv_bfloat16* xh = b_xc + base * DIk + d;
    const __nv_bfloat16* xl = xh + 2ll * Mrows * DIk;
    const float* pj  = g_proj  + base * 64 + DTRk + lane;
    const long long zrow0 = (long long)(b * Lk + (dir ? Lk - 1 : 0));
    const float* zz = g_xz + zrow0 * 4096 + dir * 2048 + 1024 + d;
    const long long zstep = dir ? -4096 : 4096;
    const long long ybase = base * DIk + d;
    const long long yplane = 2ll * Mrows * DIk;

    float A[DSk];
    bool fast = true;
    #pragma unroll
    for (int s = 0; s < DSk; s++) {
        A[s] = -expf(A_log[((long long)dir * DIk + d) * DSk + s]);
        float t = (float)(s + 1);
        if (fabsf(A[s] + t) > 1e-4f * t) fast = false;
    }
    const float Dv = Dp[dir * DIk + d];
    float h[DSk];
    #pragma unroll
    for (int s = 0; s < DSk; s++) h[s] = 0.0f;

    float rdt[RING], rxt[RING], rzt[RING], rbc[RING];
    #pragma unroll
    for (int j = 0; j < RING; j++) {
        rdt[j] = dl[(long long)j * DIk];
        rxt[j] = __bfloat162float(xh[(long long)j * DIk]) +
                 __bfloat162float(xl[(long long)j * DIk]);
        rzt[j] = zz[(long long)j * zstep];
        rbc[j] = pj[(long long)j * 64];
    }

    for (int t = 0; t < Lk; t += RING) {
        #pragma unroll
        for (int j = 0; j < RING; j++) {
            float dt = rdt[j], xt = rxt[j], zt = rzt[j], bcv = rbc[j];
            int tn = t + j + RING;
            if (tn < Lk) {
                rdt[j] = dl[(long long)tn * DIk];
                rxt[j] = __bfloat162float(xh[(long long)tn * DIk]) +
                         __bfloat162float(xl[(long long)tn * DIk]);
                rzt[j] = zz[(long long)tn * zstep];
                rbc[j] = pj[(long long)tn * 64];
            }
            float dx = dt * xt;
            float y = 0.0f;
            if (fast) {
                float e1 = __expf(-dt);
                float w = e1;
                #pragma unroll
                for (int s = 0; s < DSk; s++) {
                    float Bs = __shfl_sync(0xffffffffu, bcv, s);
                    float Cs = __shfl_sync(0xffffffffu, bcv, 16 + s);
                    h[s] = h[s] * w + dx * Bs;
                    y = fmaf(h[s], Cs, y);
                    w *= e1;
                }
            } else {
                #pragma unroll
                for (int s = 0; s < DSk; s++) {
                    float Bs = __shfl_sync(0xffffffffu, bcv, s);
                    float Cs = __shfl_sync(0xffffffffu, bcv, 16 + s);
                    h[s] = h[s] * __expf(dt * A[s]) + dx * Bs;
                    y = fmaf(h[s], Cs, y);
                }
            }
            store_bf2(b_ybuf, yplane, ybase + (long long)(t + j) * DIk,
                      (y + xt * Dv) * silu(zt));
        }
    }
}

// ---------------------------------------------------------------------------
// broadcast pos into b_cat[:, 1024:1536] planes
// ---------------------------------------------------------------------------
__global__ void posbc_kernel()
{
    long long idx = (long long)blockIdx.x * blockDim.x + threadIdx.x;
    int c = (int)(idx & (DIMk - 1));
    int m = (int)(idx >> 9);
    int l = m & (Lk - 1);
    store_bf2(b_cat, (long long)Mrows * 3 * DIMk,
              (long long)m * (3 * DIMk) + 2 * DIMk + c, g_pos[l * DIMk + c]);
}

// ---------------------------------------------------------------------------
// delta_ln = LN(mix, dn) -> fp32 dln (resid);  x2 = LN(delta_ln, fn) -> bf16
// ---------------------------------------------------------------------------
__global__ void double_ln_kernel(const float* __restrict__ dng, const float* __restrict__ dnb,
                                 const float* __restrict__ fng, const float* __restrict__ fnb)
{
    __shared__ float sbuf[8];
    const int m = blockIdx.x;
    const float* x = g_mix + (long long)m * DIMk;
    int c0 = threadIdx.x, c1 = threadIdx.x + 256;
    float v0 = x[c0], v1 = x[c1];
    float mu = block_reduce_sum_256(v0 + v1, sbuf) * (1.0f / DIMk);
    float d0 = v0 - mu, d1 = v1 - mu;
    float var = block_reduce_sum_256(d0 * d0 + d1 * d1, sbuf) * (1.0f / DIMk);
    float inv = rsqrtf(var + 1e-5f);
    float e0 = d0 * inv * dng[c0] + dnb[c0];
    float e1 = d1 * inv * dng[c1] + dnb[c1];
    g_dln[(long long)m * DIMk + c0] = e0;
    g_dln[(long long)m * DIMk + c1] = e1;
    float mu2 = block_reduce_sum_256(e0 + e1, sbuf) * (1.0f / DIMk);
    float f0 = e0 - mu2, f1 = e1 - mu2;
    float var2 = block_reduce_sum_256(f0 * f0 + f1 * f1, sbuf) * (1.0f / DIMk);
    float inv2 = rsqrtf(var2 + 1e-5f);
    const long long n = (long long)Mrows * DIMk;
    store_bf2(b_x2, n, (long long)m * DIMk + c0, f0 * inv2 * fng[c0] + fnb[c0]);
    store_bf2(b_x2, n, (long long)m * DIMk + c1, f1 * inv2 * fng[c1] + fnb[c1]);
}

// ---------------------------------------------------------------------------
// launch
// ---------------------------------------------------------------------------
extern "C" void kernel_launch(void* const* d_in, const int* in_sizes, int n_in,
                              void* d_out, int out_size)
{
    const float* tokens   = (const float*)d_in[0];
    const float* in_g     = (const float*)d_in[3];
    const float* in_b     = (const float*)d_in[4];
    const float* pos_w1   = (const float*)d_in[5];
    const float* pos_b1   = (const float*)d_in[6];
    const float* pos_w2   = (const float*)d_in[7];
    const float* pos_b2   = (const float*)d_in[8];
    const float* m_in_w   = (const float*)d_in[9];
    const float* m_conv_w = (const float*)d_in[10];
    const float* m_conv_b = (const float*)d_in[11];
    const float* m_xproj_w= (const float*)d_in[12];
    const float* m_dt_w   = (const float*)d_in[13];
    const float* m_dt_b   = (const float*)d_in[14];
    const float* m_A_log  = (const float*)d_in[15];
    const float* m_D      = (const float*)d_in[16];
    const float* m_out_w  = (const float*)d_in[17];
    const float* mix_w    = (const float*)d_in[18];
    const float* mix_b    = (const float*)d_in[19];
    const float* dn_g     = (const float*)d_in[20];
    const float* dn_b     = (const float*)d_in[21];
    const float* fn_g     = (const float*)d_in[22];
    const float* fn_b     = (const float*)d_in[23];
    const float* ffn_w1   = (const float*)d_in[24];
    const float* ffn_b1   = (const float*)d_in[25];
    const float* ffn_w2   = (const float*)d_in[26];
    const float* ffn_b2   = (const float*)d_in[27];
    float* out = (float*)d_out;

    float *p_pos, *p_xz, *p_proj, *p_delta, *p_mix, *p_dln;
    cudaGetSymbolAddress((void**)&p_pos,   g_pos);
    cudaGetSymbolAddress((void**)&p_xz,    g_xz);
    cudaGetSymbolAddress((void**)&p_proj,  g_proj);
    cudaGetSymbolAddress((void**)&p_delta, g_delta);
    cudaGetSymbolAddress((void**)&p_mix,   g_mix);
    cudaGetSymbolAddress((void**)&p_dln,   g_dln);

    __nv_bfloat16 *q_posh, *q_scanin, *q_xc, *q_proj, *q_ybuf, *q_cat, *q_x2, *q_hbuf,
                  *q_posw2, *q_inw, *q_xprojw, *q_dtw, *q_outw, *q_mixw, *q_ffn1w, *q_ffn2w;
    cudaGetSymbolAddress((void**)&q_posh,   b_posh);
    cudaGetSymbolAddress((void**)&q_scanin, b_scanin);
    cudaGetSymbolAddress((void**)&q_xc,     b_xc);
    cudaGetSymbolAddress((void**)&q_proj,   b_proj);
    cudaGetSymbolAddress((void**)&q_ybuf,   b_ybuf);
    cudaGetSymbolAddress((void**)&q_cat,    b_cat);
    cudaGetSymbolAddress((void**)&q_x2,     b_x2);
    cudaGetSymbolAddress((void**)&q_hbuf,   b_hbuf);
    cudaGetSymbolAddress((void**)&q_posw2,  b_posw2);
    cudaGetSymbolAddress((void**)&q_inw,    b_inw);
    cudaGetSymbolAddress((void**)&q_xprojw, b_xprojw);
    cudaGetSymbolAddress((void**)&q_dtw,    b_dtw);
    cudaGetSymbolAddress((void**)&q_outw,   b_outw);
    cudaGetSymbolAddress((void**)&q_mixw,   b_mixw);
    cudaGetSymbolAddress((void**)&q_ffn1w,  b_ffn1w);
    cudaGetSymbolAddress((void**)&q_ffn2w,  b_ffn2w);

    static int smem_set = 0;
    if (!smem_set) {
        cudaFuncSetAttribute(tc_gemm, cudaFuncAttributeMaxDynamicSharedMemorySize, TCG_SMEM_BYTES);
        smem_set = 1;
    }
    const int SB = TCG_SMEM_BYTES;

    // (1) fused weight conversion
    cvt_all_kernel<<<(WTOT / 4 + 255) / 256, 256>>>(pos_w2, m_in_w, m_xproj_w, m_dt_w,
                                                    m_out_w, mix_w, ffn_w1, ffn_w2);
    // (2) pos features, (3) pos GEMM
    pos_feat_kernel<<<Lk, DIMk>>>(pos_w1, pos_b1);
    tc_gemm<<<dim3(4, 8), 256, SB>>>(q_posh, (long long)Lk * DIMk, DIMk,
                                     q_posw2, (long long)DIMk * DIMk,
                                     pos_b2, nullptr, p_pos, nullptr, 0,
                                     Lk, DIMk, DIMk, DIMk, 0, 1);
    // (4) scan_in = LN(tokens)+pos
    ln_add_pos_kernel<<<Mrows, 256>>>(tokens, in_g, in_b);
    // (5) pos broadcast into cat third slice (independent; placed here so the
    //     merged in_proj below is launch #6 = the one ncu captures)
    posbc_kernel<<<(unsigned)(((long long)Mrows * DIMk + 255) / 256), 256>>>();

    // (6) merged in_proj: one GEMM, N=4096 (both dirs)
    tc_gemm<<<dim3(32, 64), 256, SB>>>(
        q_scanin, (long long)Mrows * DIMk, DIMk,
        q_inw, (long long)4096 * DIMk,
        nullptr, nullptr,
        p_xz, nullptr, 0,
        Mrows, 4096, DIMk, 4096, 0, 0);

    // (7) conv + silu (handles dir1 time reversal)
    conv_kernel<<<(unsigned)((2ll * Mrows * DIk + 255) / 256), 256>>>(m_conv_w, m_conv_b);

    // (8-11) x_proj / dt proj per dir
    for (int dir = 0; dir < 2; dir++) {
        tc_gemm<<<dim3(1, 64), 256, SB>>>(
            q_xc + (long long)dir * Mrows * DIk, 2ll * Mrows * DIk, DIk,
            q_xprojw + (long long)dir * 64 * DIk, 2ll * 64 * DIk,
            nullptr, nullptr,
            p_proj + (long long)dir * Mrows * 64,
            q_proj + (long long)dir * Mrows * 64, 2ll * Mrows * 64,
            Mrows, 64, DIk, 64, 0, 0);
        tc_gemm<<<dim3(8, 64), 256, SB>>>(
            q_proj + (long long)dir * Mrows * 64, 2ll * Mrows * 64, 64,
            q_dtw + (long long)dir * DIk * DTRk, 2ll * DIk * DTRk,
            m_dt_b + dir * DIk, nullptr,
            p_delta + (long long)dir * Mrows * DIk, nullptr, 0,
            Mrows, DIk, DTRk, DIk, 0, 4);
    }
    // (12) selective scan + gating -> bf16 ybuf
    scan_kernel<<<128, 128>>>(m_A_log, m_D);

    // (13,14) out_proj -> bf16 cat slices (bwd un-reversed on store)
    for (int dir = 0; dir < 2; dir++) {
        tc_gemm<<<dim3(4, 64), 256, SB>>>(
            q_ybuf + (long long)dir * Mrows * DIk, 2ll * Mrows * DIk, DIk,
            q_outw + (long long)dir * DIMk * DIk, 2ll * DIMk * DIk,
            nullptr, nullptr,
            nullptr, q_cat + dir * DIMk, (long long)Mrows * 3 * DIMk,
            Mrows, DIMk, DIk, 3 * DIMk, dir, 0);
    }

    // (15) mix GEMM
    tc_gemm<<<dim3(4, 64), 256, SB>>>(
        q_cat, (long long)Mrows * 3 * DIMk, 3 * DIMk,
        q_mixw, (long long)DIMk * 3 * DIMk,
        mix_b, nullptr, p_mix, nullptr, 0,
        Mrows, DIMk, 3 * DIMk, DIMk, 0, 1);
    // (16) double LN
    double_ln_kernel<<<Mrows, 256>>>(dn_g, dn_b, fn_g, fn_b);

    // (17,18) FFN
    tc_gemm<<<dim3(8, 64), 256, SB>>>(
        q_x2, (long long)Mrows * DIMk, DIMk,
        q_ffn1w, (long long)HIDk * DIMk,
        ffn_b1, nullptr, nullptr, q_hbuf, (long long)Mrows * HIDk,
        Mrows, HIDk, DIMk, HIDk, 0, 2);
    tc_gemm<<<dim3(4, 64), 256, SB>>>(
        q_hbuf, (long long)Mrows * HIDk, HIDk,
        q_ffn2w, (long long)DIMk * HIDk,
        ffn_b2, p_dln, out, nullptr, 0,
        Mrows, DIMk, HIDk, DIMk, 0, 3);
    (void)in_sizes; (void)n_in; (void)out_size;
}

// round 14
// speedup vs baseline: 2.0352x; 1.0821x over previous
#include <cuda_runtime.h>
#include <cuda_bf16.h>
#include <math.h>
#include <stdint.h>

// ---------------------------------------------------------------------------
// Problem constants
// ---------------------------------------------------------------------------
#define Bk     8
#define Hh     32
#define Ww     32
#define Lk     1024
#define DIMk   512
#define DSk    16
#define DCONVk 4
#define DIk    1024
#define DTRk   32
#define HIDk   1024
#define Mrows  (Bk*Lk)          // 8192

// ---------------------------------------------------------------------------
// fp32 scratch
// ---------------------------------------------------------------------------
__device__ float g_pos[Lk * DIMk];
__device__ float g_posmix[Lk * DIMk];
__device__ float g_xz[(long long)Mrows * 4096];   // [8192][4096]: dir*2048 + (xin|z)
__device__ float g_proj[2ll * Mrows * 64];
__device__ float g_delta[2ll * Mrows * DIk];
__device__ float g_mix[Mrows * DIMk];
__device__ float g_dln[Mrows * DIMk];

// ---------------------------------------------------------------------------
// bf16 hi/lo split buffers: [hi plane (n elems) | lo plane (n elems)]
// ---------------------------------------------------------------------------
__device__ __nv_bfloat16 b_posh  [2ll * Lk * DIMk];
__device__ __nv_bfloat16 b_posf  [2ll * Lk * DIMk];
__device__ __nv_bfloat16 b_scanin[2ll * Mrows * DIMk];
__device__ __nv_bfloat16 b_xc    [2ll * 2 * Mrows * DIk];
__device__ __nv_bfloat16 b_proj  [2ll * 2 * Mrows * 64];
__device__ __nv_bfloat16 b_ybuf  [2ll * 2 * Mrows * DIk];
__device__ __nv_bfloat16 b_cat   [2ll * Mrows * 2 * DIMk];   // [8192][fwd512|bwd512]
__device__ __nv_bfloat16 b_x2    [2ll * Mrows * DIMk];
__device__ __nv_bfloat16 b_hbuf  [2ll * Mrows * HIDk];
// weights
__device__ __nv_bfloat16 b_posw2 [2ll * DIMk * DIMk];
__device__ __nv_bfloat16 b_inw   [2ll * 4096 * DIMk];
__device__ __nv_bfloat16 b_xprojw[2ll * 2 * 64 * DIk];
__device__ __nv_bfloat16 b_dtw   [2ll * 2 * DIk * DTRk];
__device__ __nv_bfloat16 b_outw  [2ll * 2 * DIMk * DIk];
__device__ __nv_bfloat16 b_mixw  [2ll * DIMk * 3 * DIMk];
__device__ __nv_bfloat16 b_ffn1w [2ll * HIDk * DIMk];
__device__ __nv_bfloat16 b_ffn2w [2ll * DIMk * HIDk];

// ---------------------------------------------------------------------------
// Helpers (sm_80-era PTX only)
// ---------------------------------------------------------------------------
__device__ __forceinline__ uint32_t smem_to_u32(const void* p) {
    uint32_t a;
    asm("{ .reg .u64 t; cvta.to.shared.u64 t, %1; cvt.u32.u64 %0, t; }" : "=r"(a) : "l"(p));
    return a;
}
__device__ __forceinline__ void ldsm4(uint32_t* r, uint32_t addr) {
    asm volatile("ldmatrix.sync.aligned.m8n8.x4.shared.b16 {%0,%1,%2,%3}, [%4];"
                 : "=r"(r[0]), "=r"(r[1]), "=r"(r[2]), "=r"(r[3]) : "r"(addr));
}
__device__ __forceinline__ void mma_bf16(float* c, const uint32_t* a, uint32_t b0, uint32_t b1) {
    asm volatile("mma.sync.aligned.m16n8k16.row.col.f32.bf16.bf16.f32 "
                 "{%0,%1,%2,%3}, {%4,%5,%6,%7}, {%8,%9}, {%0,%1,%2,%3};"
                 : "+f"(c[0]), "+f"(c[1]), "+f"(c[2]), "+f"(c[3])
                 : "r"(a[0]), "r"(a[1]), "r"(a[2]), "r"(a[3]), "r"(b0), "r"(b1));
}
__device__ __forceinline__ void cp_async16(uint32_t dst, const void* src, int srcsize) {
    asm volatile("cp.async.ca.shared.global [%0], [%1], 16, %2;"
                 :: "r"(dst), "l"(src), "r"(srcsize) : "memory");
}
#define CP_COMMIT() asm volatile("cp.async.commit_group;" ::: "memory")
#define CP_WAIT1()  asm volatile("cp.async.wait_group 1;" ::: "memory")

__device__ __forceinline__ uint32_t bf16pack(float e0, float e1) { // e0 -> low half
    uint32_t r; asm("cvt.rn.bf16x2.f32 %0, %1, %2;" : "=r"(r) : "f"(e1), "f"(e0)); return r;
}
__device__ __forceinline__ float bf16lo_as_f32(uint32_t p) { return __uint_as_float(p << 16); }
__device__ __forceinline__ float bf16hi_as_f32(uint32_t p) { return __uint_as_float(p & 0xffff0000u); }

__device__ __forceinline__ float gelu_exact(float x) {
    return 0.5f * x * (1.0f + erff(x * 0.70710678118654752f));
}
__device__ __forceinline__ float silu(float x) { return x / (1.0f + __expf(-x)); }

__device__ __forceinline__ void store_bf2(__nv_bfloat16* base, long long plane,
                                          long long idx, float v) {
    __nv_bfloat16 h = __float2bfloat16(v);
    base[idx] = h;
    base[plane + idx] = __float2bfloat16(v - __bfloat162float(h));
}

__device__ __forceinline__ float block_reduce_sum_256(float v, float* sbuf) {
    int lane = threadIdx.x & 31, w = threadIdx.x >> 5;
    #pragma unroll
    for (int o = 16; o; o >>= 1) v += __shfl_down_sync(0xffffffffu, v, o);
    if (lane == 0) sbuf[w] = v;
    __syncthreads();
    float r = (threadIdx.x < 8) ? sbuf[threadIdx.x] : 0.0f;
    if (w == 0) {
        #pragma unroll
        for (int o = 4; o; o >>= 1) r += __shfl_down_sync(0xffu, r, o);
        if (lane == 0) sbuf[0] = r;
    }
    __syncthreads();
    float out = sbuf[0];
    __syncthreads();
    return out;
}

// ---------------------------------------------------------------------------
// Fused weight conversion
// ---------------------------------------------------------------------------
#define WS0 (DIMk*DIMk)
#define WS1 (4096*DIMk)
#define WS2 (2*64*DIk)
#define WS3 (2*DIk*DTRk)
#define WS4 (2*DIMk*DIk)
#define WS5 (DIMk*3*DIMk)
#define WS6 (HIDk*DIMk)
#define WS7 (DIMk*HIDk)
#define WP1 (WS0)
#define WP2 (WP1+WS1)
#define WP3 (WP2+WS2)
#define WP4 (WP3+WS3)
#define WP5 (WP4+WS4)
#define WP6 (WP5+WS5)
#define WP7 (WP6+WS6)
#define WTOT (WP7+WS7)

__global__ void cvt_all_kernel(const float* __restrict__ s0, const float* __restrict__ s1,
                               const float* __restrict__ s2, const float* __restrict__ s3,
                               const float* __restrict__ s4, const float* __restrict__ s5,
                               const float* __restrict__ s6, const float* __restrict__ s7)
{
    long long base = ((long long)blockIdx.x * blockDim.x + threadIdx.x) * 4;
    if (base >= WTOT) return;
    const float* src; __nv_bfloat16* dst; long long off; long long n;
    if      (base < WP1) { src = s0; dst = b_posw2;  off = base;       n = WS0; }
    else if (base < WP2) { src = s1; dst = b_inw;    off = base - WP1; n = WS1; }
    else if (base < WP3) { src = s2; dst = b_xprojw; off = base - WP2; n = WS2; }
    else if (base < WP4) { src = s3; dst = b_dtw;    off = base - WP3; n = WS3; }
    else if (base < WP5) { src = s4; dst = b_outw;   off = base - WP4; n = WS4; }
    else if (base < WP6) { src = s5; dst = b_mixw;   off = base - WP5; n = WS5; }
    else if (base < WP7) { src = s6; dst = b_ffn1w;  off = base - WP6; n = WS6; }
    else                 { src = s7; dst = b_ffn2w;  off = base - WP7; n = WS7; }
    float4 v = *reinterpret_cast<const float4*>(src + off);
    store_bf2(dst, n, off + 0, v.x);
    store_bf2(dst, n, off + 1, v.y);
    store_bf2(dst, n, off + 2, v.z);
    store_bf2(dst, n, off + 3, v.w);
}

// ---------------------------------------------------------------------------
// bf16x3 mma.sync GEMM, cp.async 3-stage pipeline, 12-ldsm inner loop.
//   Dual-M mode (cmode=1): blocks with m0>=Mrows use W+wsel / bias+bsel,
//   write C rows (gm-Mrows) time-reversed within 1024, columns +N.
//   epi: 0 none, 1 +bias, 2 gelu(+bias), 3 +bias+resid, 4 softplus(+bias),
//        5 +resid only (resid row = gm & rmask)
// ---------------------------------------------------------------------------
#define KC      32
#define NSTAGE  3
#define STB     32768
#define TCG_SMEM_BYTES (NSTAGE * STB)

__device__ __forceinline__ void issue_stage(
    uint32_t sbase, int s,
    const __nv_bfloat16* __restrict__ A, long long aplane, int lda,
    const __nv_bfloat16* __restrict__ W, long long wplane, int ldw,
    int m0, int n0, int N, int kidx, int tid)
{
    const int k0 = kidx * KC;
    const uint32_t st = sbase + (uint32_t)s * STB;
    #pragma unroll
    for (int it = 0; it < 8; it++) {
        int task = tid + it * 256;
        int plane = task >> 9;
        int rem = task & 511;
        int row = rem >> 2;
        int ch = rem & 3;
        int phys = ch ^ ((row >> 1) & 3);
        uint32_t sdst = st + (uint32_t)plane * 8192u + (uint32_t)(row * 64 + phys * 16);
        const __nv_bfloat16* src;
        int size = 16;
        if (plane < 2) {
            int gm = m0 + row;
            src = A + (plane ? aplane : 0) + (long long)gm * lda + k0 + ch * 8;
        } else {
            int gn = n0 + row;
            if (gn >= N) { gn = N - 1; size = 0; }
            src = W + (plane == 3 ? wplane : 0) + (long long)gn * ldw + k0 + ch * 8;
        }
        cp_async16(sdst, src, size);
    }
}

__device__ __forceinline__ void mma_tile(float acc[4][4][4],
                                         uint32_t a[4][4], uint32_t b[2][4]) {
    #pragma unroll
    for (int mt = 0; mt < 4; mt++)
        #pragma unroll
        for (int nt = 0; nt < 4; nt++)
            mma_bf16(acc[mt][nt], a[mt], b[nt >> 1][nt & 1], b[nt >> 1][2 + (nt & 1)]);
}

__global__ __launch_bounds__(256, 2)
void tc_gemm(const __nv_bfloat16* __restrict__ A, long long aplane, int lda,
             const __nv_bfloat16* __restrict__ W, long long wplane, int ldw, long long wsel,
             const float* __restrict__ bias, int bsel,
             const float* __restrict__ resid, unsigned rmask,
             float* __restrict__ C, __nv_bfloat16* __restrict__ Cb, long long cplane,
             int M, int N, int K, int ldc, int cmode, int epi)
{
    extern __shared__ char smem[];
    const uint32_t sbase = smem_to_u32(smem);
    const int tid = threadIdx.x, lane = tid & 31, wid = tid >> 5;
    const int m0 = blockIdx.y * 128, n0 = blockIdx.x * 128;
    const int warpM = (wid & 1) * 64, warpN = (wid >> 1) * 32;
    const uint32_t rsel = (uint32_t)(lane & 15);
    const uint32_t ksel = (uint32_t)(lane >> 4);

    const int upper = (m0 >= Mrows);
    if (upper) { W += wsel; if (bias) bias += bsel; }
    const int coladd = (cmode == 1 && upper) ? N : 0;

    uint32_t aoff[4], asw[4], boff[2], bsw[2];
    #pragma unroll
    for (int mt = 0; mt < 4; mt++) {
        uint32_t r = (uint32_t)warpM + mt * 16u + rsel;
        aoff[mt] = r * 64u; asw[mt] = (r >> 1) & 3u;
    }
    #pragma unroll
    for (int p = 0; p < 2; p++) {
        uint32_t r = (uint32_t)warpN + p * 16u + rsel;
        boff[p] = r * 64u; bsw[p] = (r >> 1) & 3u;
    }

    float acc[4][4][4];
    #pragma unroll
    for (int i = 0; i < 4; i++)
        #pragma unroll
        for (int j = 0; j < 4; j++)
            #pragma unroll
            for (int r = 0; r < 4; r++) acc[i][j][r] = 0.0f;

    const int nch = K / KC;
    #pragma unroll
    for (int s = 0; s < NSTAGE - 1; s++) {
        if (s < nch) issue_stage(sbase, s, A, aplane, lda, W, wplane, ldw, m0, n0, N, s, tid);
        CP_COMMIT();
    }

    for (int c = 0; c < nch; c++) {
        CP_WAIT1();
        __syncthreads();
        int nxt = c + NSTAGE - 1;
        if (nxt < nch)
            issue_stage(sbase, nxt % NSTAGE, A, aplane, lda, W, wplane, ldw, m0, n0, N, nxt, tid);
        CP_COMMIT();

        const uint32_t st = sbase + (uint32_t)(c % NSTAGE) * STB;
        #pragma unroll
        for (int ks = 0; ks < 2; ks++) {
            const uint32_t chunk = (uint32_t)(ks * 2) + ksel;
            uint32_t a[4][4], bhi[2][4], blo[2][4];
            #pragma unroll
            for (int mt = 0; mt < 4; mt++)
                ldsm4(a[mt], st + aoff[mt] + (((chunk ^ asw[mt]) << 4)));
            #pragma unroll
            for (int p = 0; p < 2; p++)
                ldsm4(bhi[p], st + 16384u + boff[p] + (((chunk ^ bsw[p]) << 4)));
            #pragma unroll
            for (int p = 0; p < 2; p++)
                ldsm4(blo[p], st + 24576u + boff[p] + (((chunk ^ bsw[p]) << 4)));
            mma_tile(acc, a, bhi);
            mma_tile(acc, a, blo);
            #pragma unroll
            for (int mt = 0; mt < 4; mt++)
                ldsm4(a[mt], st + 8192u + aoff[mt] + (((chunk ^ asw[mt]) << 4)));
            mma_tile(acc, a, bhi);
        }
    }

    // ---- epilogue ----
    #pragma unroll
    for (int mt = 0; mt < 4; mt++) {
        int r0 = m0 + warpM + mt * 16 + (lane >> 2);
        #pragma unroll
        for (int half = 0; half < 2; half++) {
            int gm = r0 + half * 8;
            if (cmode == 1 && upper) {
                int t = gm - Mrows;
                gm = (t & ~(Lk - 1)) + (Lk - 1 - (t & (Lk - 1)));
            }
            #pragma unroll
            for (int nt = 0; nt < 4; nt++) {
                int ncol = n0 + warpN + nt * 8 + (lane & 3) * 2;
                if (ncol >= N) continue;
                float v0 = acc[mt][nt][half * 2 + 0];
                float v1 = acc[mt][nt][half * 2 + 1];
                if (epi >= 1 && epi <= 4) { v0 += bias[ncol]; v1 += bias[ncol + 1]; }
                if (epi == 2) { v0 = gelu_exact(v0); v1 = gelu_exact(v1); }
                else if (epi == 4) {
                    v0 = (v0 > 20.0f) ? v0 : log1pf(__expf(v0));
                    v1 = (v1 > 20.0f) ? v1 : log1pf(__expf(v1));
                } else if (epi == 3 || epi == 5) {
                    const float* rp = resid + (long long)(gm & rmask) * ldc + ncol;
                    v0 += rp[0]; v1 += rp[1];
                }
                long long o = (long long)gm * ldc + ncol + coladd;
                if (C) *reinterpret_cast<float2*>(C + o) = make_float2(v0, v1);
                if (Cb) {
                    uint32_t hp = bf16pack(v0, v1);
                    *reinterpret_cast<uint32_t*>(Cb + o) = hp;
                    *reinterpret_cast<uint32_t*>(Cb + cplane + o) =
                        bf16pack(v0 - bf16lo_as_f32(hp), v1 - bf16hi_as_f32(hp));
                }
            }
        }
    }
}

// ---------------------------------------------------------------------------
// pos features -> bf16 planes
// ---------------------------------------------------------------------------
__global__ void pos_feat_kernel(const float* __restrict__ w1, const float* __restrict__ b1)
{
    const int l = blockIdx.x;
    const int j = threadIdx.x;
    const float PI = 3.14159265358979323846f;
    float yy = ((float)(l >> 5) + 0.5f) / (float)Hh * 2.0f - 1.0f;
    float xx = ((float)(l & 31) + 0.5f) / (float)Ww * 2.0f - 1.0f;
    float p2 = sinf(PI * yy), p3 = cosf(PI * yy);
    float p4 = sinf(PI * xx), p5 = cosf(PI * xx);
    const float* w = w1 + j * 6;
    float a = yy * w[0] + xx * w[1] + p2 * w[2] + p3 * w[3] + p4 * w[4] + p5 * w[5] + b1[j];
    store_bf2(b_posh, (long long)Lk * DIMk, (long long)l * DIMk + j, gelu_exact(a));
}

// ---------------------------------------------------------------------------
// scan_in = LN(tokens) + pos  -> bf16 planes
// ---------------------------------------------------------------------------
__global__ void ln_add_pos_kernel(const float* __restrict__ tokens,
                                  const float* __restrict__ g, const float* __restrict__ b)
{
    __shared__ float sbuf[8];
    const int m = blockIdx.x;
    const int l = m & (Lk - 1);
    const float* x = tokens + (long long)m * DIMk;
    int c0 = threadIdx.x, c1 = threadIdx.x + 256;
    float v0 = x[c0], v1 = x[c1];
    float mu = block_reduce_sum_256(v0 + v1, sbuf) * (1.0f / DIMk);
    float d0 = v0 - mu, d1 = v1 - mu;
    float var = block_reduce_sum_256(d0 * d0 + d1 * d1, sbuf) * (1.0f / DIMk);
    float inv = rsqrtf(var + 1e-5f);
    const long long n = (long long)Mrows * DIMk;
    store_bf2(b_scanin, n, (long long)m * DIMk + c0, d0 * inv * g[c0] + b[c0] + g_pos[l * DIMk + c0]);
    store_bf2(b_scanin, n, (long long)m * DIMk + c1, d1 * inv * g[c1] + b[c1] + g_pos[l * DIMk + c1]);
}

// ---------------------------------------------------------------------------
// causal depthwise conv + silu (dir1 time-reversed read from merged g_xz)
// ---------------------------------------------------------------------------
__global__ void conv_kernel(const float* __restrict__ cw, const float* __restrict__ cb)
{
    long long idx = (long long)blockIdx.x * blockDim.x + threadIdx.x;
    if (idx >= 2ll * Mrows * DIk) return;
    int d   = (int)(idx & (DIk - 1));
    long long m = idx >> 10;
    int dir = (int)(m >> 13);
    int bl  = (int)(m & (Mrows - 1));
    int l   = bl & (Lk - 1);
    int brow = bl & ~(Lk - 1);
    const float* w = cw + ((long long)dir * DIk + d) * DCONVk;
    float acc = cb[dir * DIk + d];
    #pragma unroll
    for (int k = 0; k < DCONVk; k++) {
        int s = l - (DCONVk - 1) + k;
        if (s >= 0) {
            int row = brow + (dir ? (Lk - 1 - s) : s);
            acc += g_xz[(long long)row * 4096 + dir * 2048 + d] * w[k];
        }
    }
    store_bf2(b_xc, 2ll * Mrows * DIk, idx, silu(acc));
}

// ---------------------------------------------------------------------------
// selective scan: shuffle-broadcast B/C, ring-8 prefetch, fast exp path
// ---------------------------------------------------------------------------
#define RING 8
__global__ __launch_bounds__(128)
void scan_kernel(const float* __restrict__ A_log, const float* __restrict__ Dp)
{
    const int blk = blockIdx.x;
    const int dir = blk >> 6;
    const int b   = (blk >> 3) & 7;
    const int d   = ((blk & 7) << 7) + threadIdx.x;
    const int lane = threadIdx.x & 31;

    const long long base = ((long long)dir * Mrows + (long long)b * Lk);
    const float* dl  = g_delta + base * DIk + d;
    const __nv_bfloat16* xh = b_xc + base * DIk + d;
    const __nv_bfloat16* xl = xh + 2ll * Mrows * DIk;
    const float* pj  = g_proj  + base * 64 + DTRk + lane;
    const long long zrow0 = (long long)(b * Lk + (dir ? Lk - 1 : 0));
    const float* zz = g_xz + zrow0 * 4096 + dir * 2048 + 1024 + d;
    const long long zstep = dir ? -4096 : 4096;
    const long long ybase = base * DIk + d;
    const long long yplane = 2ll * Mrows * DIk;

    float A[DSk];
    bool fast = true;
    #pragma unroll
    for (int s = 0; s < DSk; s++) {
        A[s] = -expf(A_log[((long long)dir * DIk + d) * DSk + s]);
        float t = (float)(s + 1);
        if (fabsf(A[s] + t) > 1e-4f * t) fast = false;
    }
    const float Dv = Dp[dir * DIk + d];
    float h[DSk];
    #pragma unroll
    for (int s = 0; s < DSk; s++) h[s] = 0.0f;

    float rdt[RING], rxt[RING], rzt[RING], rbc[RING];
    #pragma unroll
    for (int j = 0; j < RING; j++) {
        rdt[j] = dl[(long long)j * DIk];
        rxt[j] = __bfloat162float(xh[(long long)j * DIk]) +
                 __bfloat162float(xl[(long long)j * DIk]);
        rzt[j] = zz[(long long)j * zstep];
        rbc[j] = pj[(long long)j * 64];
    }

    for (int t = 0; t < Lk; t += RING) {
        #pragma unroll
        for (int j = 0; j < RING; j++) {
            float dt = rdt[j], xt = rxt[j], zt = rzt[j], bcv = rbc[j];
            int tn = t + j + RING;
            if (tn < Lk) {
                rdt[j] = dl[(long long)tn * DIk];
                rxt[j] = __bfloat162float(xh[(long long)tn * DIk]) +
                         __bfloat162float(xl[(long long)tn * DIk]);
                rzt[j] = zz[(long long)tn * zstep];
                rbc[j] = pj[(long long)tn * 64];
            }
            float dx = dt * xt;
            float y = 0.0f;
            if (fast) {
                float e1 = __expf(-dt);
                float w = e1;
                #pragma unroll
                for (int s = 0; s < DSk; s++) {
                    float Bs = __shfl_sync(0xffffffffu, bcv, s);
                    float Cs = __shfl_sync(0xffffffffu, bcv, 16 + s);
                    h[s] = h[s] * w + dx * Bs;
                    y = fmaf(h[s], Cs, y);
                    w *= e1;
                }
            } else {
                #pragma unroll
                for (int s = 0; s < DSk; s++) {
                    float Bs = __shfl_sync(0xffffffffu, bcv, s);
                    float Cs = __shfl_sync(0xffffffffu, bcv, 16 + s);
                    h[s] = h[s] * __expf(dt * A[s]) + dx * Bs;
                    y = fmaf(h[s], Cs, y);
                }
            }
            store_bf2(b_ybuf, yplane, ybase + (long long)(t + j) * DIk,
                      (y + xt * Dv) * silu(zt));
        }
    }
}

// ---------------------------------------------------------------------------
// delta_ln = LN(mix, dn) -> fp32 dln (resid);  x2 = LN(delta_ln, fn) -> bf16
// ---------------------------------------------------------------------------
__global__ void double_ln_kernel(const float* __restrict__ dng, const float* __restrict__ dnb,
                                 const float* __restrict__ fng, const float* __restrict__ fnb)
{
    __shared__ float sbuf[8];
    const int m = blockIdx.x;
    const float* x = g_mix + (long long)m * DIMk;
    int c0 = threadIdx.x, c1 = threadIdx.x + 256;
    float v0 = x[c0], v1 = x[c1];
    float mu = block_reduce_sum_256(v0 + v1, sbuf) * (1.0f / DIMk);
    float d0 = v0 - mu, d1 = v1 - mu;
    float var = block_reduce_sum_256(d0 * d0 + d1 * d1, sbuf) * (1.0f / DIMk);
    float inv = rsqrtf(var + 1e-5f);
    float e0 = d0 * inv * dng[c0] + dnb[c0];
    float e1 = d1 * inv * dng[c1] + dnb[c1];
    g_dln[(long long)m * DIMk + c0] = e0;
    g_dln[(long long)m * DIMk + c1] = e1;
    float mu2 = block_reduce_sum_256(e0 + e1, sbuf) * (1.0f / DIMk);
    float f0 = e0 - mu2, f1 = e1 - mu2;
    float var2 = block_reduce_sum_256(f0 * f0 + f1 * f1, sbuf) * (1.0f / DIMk);
    float inv2 = rsqrtf(var2 + 1e-5f);
    const long long n = (long long)Mrows * DIMk;
    store_bf2(b_x2, n, (long long)m * DIMk + c0, f0 * inv2 * fng[c0] + fnb[c0]);
    store_bf2(b_x2, n, (long long)m * DIMk + c1, f1 * inv2 * fng[c1] + fnb[c1]);
}

// ---------------------------------------------------------------------------
// launch
// ---------------------------------------------------------------------------
extern "C" void kernel_launch(void* const* d_in, const int* in_sizes, int n_in,
                              void* d_out, int out_size)
{
    const float* tokens   = (const float*)d_in[0];
    const float* in_g     = (const float*)d_in[3];
    const float* in_b     = (const float*)d_in[4];
    const float* pos_w1   = (const float*)d_in[5];
    const float* pos_b1   = (const float*)d_in[6];
    const float* pos_w2   = (const float*)d_in[7];
    const float* pos_b2   = (const float*)d_in[8];
    const float* m_in_w   = (const float*)d_in[9];
    const float* m_conv_w = (const float*)d_in[10];
    const float* m_conv_b = (const float*)d_in[11];
    const float* m_xproj_w= (const float*)d_in[12];
    const float* m_dt_w   = (const float*)d_in[13];
    const float* m_dt_b   = (const float*)d_in[14];
    const float* m_A_log  = (const float*)d_in[15];
    const float* m_D      = (const float*)d_in[16];
    const float* m_out_w  = (const float*)d_in[17];
    const float* mix_w    = (const float*)d_in[18];
    const float* mix_b    = (const float*)d_in[19];
    const float* dn_g     = (const float*)d_in[20];
    const float* dn_b     = (const float*)d_in[21];
    const float* fn_g     = (const float*)d_in[22];
    const float* fn_b     = (const float*)d_in[23];
    const float* ffn_w1   = (const float*)d_in[24];
    const float* ffn_b1   = (const float*)d_in[25];
    const float* ffn_w2   = (const float*)d_in[26];
    const float* ffn_b2   = (const float*)d_in[27];
    float* out = (float*)d_out;

    float *p_pos, *p_posmix, *p_xz, *p_proj, *p_delta, *p_mix, *p_dln;
    cudaGetSymbolAddress((void**)&p_pos,    g_pos);
    cudaGetSymbolAddress((void**)&p_posmix, g_posmix);
    cudaGetSymbolAddress((void**)&p_xz,     g_xz);
    cudaGetSymbolAddress((void**)&p_proj,   g_proj);
    cudaGetSymbolAddress((void**)&p_delta,  g_delta);
    cudaGetSymbolAddress((void**)&p_mix,    g_mix);
    cudaGetSymbolAddress((void**)&p_dln,    g_dln);

    __nv_bfloat16 *q_posh, *q_posf, *q_scanin, *q_xc, *q_proj, *q_ybuf, *q_cat, *q_x2, *q_hbuf,
                  *q_posw2, *q_inw, *q_xprojw, *q_dtw, *q_outw, *q_mixw, *q_ffn1w, *q_ffn2w;
    cudaGetSymbolAddress((void**)&q_posh,   b_posh);
    cudaGetSymbolAddress((void**)&q_posf,   b_posf);
    cudaGetSymbolAddress((void**)&q_scanin, b_scanin);
    cudaGetSymbolAddress((void**)&q_xc,     b_xc);
    cudaGetSymbolAddress((void**)&q_proj,   b_proj);
    cudaGetSymbolAddress((void**)&q_ybuf,   b_ybuf);
    cudaGetSymbolAddress((void**)&q_cat,    b_cat);
    cudaGetSymbolAddress((void**)&q_x2,     b_x2);
    cudaGetSymbolAddress((void**)&q_hbuf,   b_hbuf);
    cudaGetSymbolAddress((void**)&q_posw2,  b_posw2);
    cudaGetSymbolAddress((void**)&q_inw,    b_inw);
    cudaGetSymbolAddress((void**)&q_xprojw, b_xprojw);
    cudaGetSymbolAddress((void**)&q_dtw,    b_dtw);
    cudaGetSymbolAddress((void**)&q_outw,   b_outw);
    cudaGetSymbolAddress((void**)&q_mixw,   b_mixw);
    cudaGetSymbolAddress((void**)&q_ffn1w,  b_ffn1w);
    cudaGetSymbolAddress((void**)&q_ffn2w,  b_ffn2w);

    static int smem_set = 0;
    if (!smem_set) {
        cudaFuncSetAttribute(tc_gemm, cudaFuncAttributeMaxDynamicSharedMemorySize, TCG_SMEM_BYTES);
        smem_set = 1;
    }
    const int SB = TCG_SMEM_BYTES;
    const unsigned RMALL = 0x7FFFFFFFu;

    // (1) fused weight conversion
    cvt_all_kernel<<<(WTOT / 4 + 255) / 256, 256>>>(pos_w2, m_in_w, m_xproj_w, m_dt_w,
                                                    m_out_w, mix_w, ffn_w1, ffn_w2);
    // (2) pos features, (3) pos GEMM (fp32 + bf16 planes)
    pos_feat_kernel<<<Lk, DIMk>>>(pos_w1, pos_b1);
    tc_gemm<<<dim3(4, 8), 256, SB>>>(q_posh, (long long)Lk * DIMk, DIMk,
                                     q_posw2, (long long)DIMk * DIMk, DIMk, 0,
                                     pos_b2, 0, nullptr, 0,
                                     p_pos, q_posf, (long long)Lk * DIMk,
                                     Lk, DIMk, DIMk, DIMk, 0, 1);
    // (4) posmix = pos @ mix_w[:,1024:1536]^T + mix_b   (per-l, batch-invariant)
    tc_gemm<<<dim3(4, 8), 256, SB>>>(q_posf, (long long)Lk * DIMk, DIMk,
                                     q_mixw + 2 * DIMk, (long long)DIMk * 3 * DIMk, 3 * DIMk, 0,
                                     mix_b, 0, nullptr, 0,
                                     p_posmix, nullptr, 0,
                                     Lk, DIMk, DIMk, DIMk, 0, 1);
    // (5) scan_in = LN(tokens)+pos
    ln_add_pos_kernel<<<Mrows, 256>>>(tokens, in_g, in_b);

    // (6) merged in_proj: one GEMM, N=4096 (both dirs)
    tc_gemm<<<dim3(32, 64), 256, SB>>>(
        q_scanin, (long long)Mrows * DIMk, DIMk,
        q_inw, (long long)4096 * DIMk, DIMk, 0,
        nullptr, 0, nullptr, 0,
        p_xz, nullptr, 0,
        Mrows, 4096, DIMk, 4096, 0, 0);

    // (7) conv + silu
    conv_kernel<<<(unsigned)((2ll * Mrows * DIk + 255) / 256), 256>>>(m_conv_w, m_conv_b);

    // (8) x_proj, M-merged both dirs (W switched at m0>=8192)
    tc_gemm<<<dim3(1, 128), 256, SB>>>(
        q_xc, 2ll * Mrows * DIk, DIk,
        q_xprojw, 2ll * 64 * DIk, DIk, (long long)64 * DIk,
        nullptr, 0, nullptr, 0,
        p_proj, q_proj, 2ll * Mrows * 64,
        2 * Mrows, 64, DIk, 64, 0, 0);
    // (9) dt proj + softplus, M-merged
    tc_gemm<<<dim3(8, 128), 256, SB>>>(
        q_proj, 2ll * Mrows * 64, 64,
        q_dtw, 2ll * DIk * DTRk, DTRk, (long long)DIk * DTRk,
        m_dt_b, DIk, nullptr, 0,
        p_delta, nullptr, 0,
        2 * Mrows, DIk, DTRk, DIk, 0, 4);

    // (10) selective scan + gating -> bf16 ybuf
    scan_kernel<<<128, 128>>>(m_A_log, m_D);

    // (11) out_proj, M-merged dual-output (upper half -> cat cols 512..1023,
    //      rows time-un-reversed)
    tc_gemm<<<dim3(4, 128), 256, SB>>>(
        q_ybuf, 2ll * Mrows * DIk, DIk,
        q_outw, 2ll * DIMk * DIk, DIk, (long long)DIMk * DIk,
        nullptr, 0, nullptr, 0,
        nullptr, q_cat, (long long)Mrows * 2 * DIMk,
        2 * Mrows, DIMk, DIk, 2 * DIMk, 1, 0);

    // (12) mix GEMM: K=1024 (fwd|bwd), pos part added via posmix residual
    tc_gemm<<<dim3(4, 64), 256, SB>>>(
        q_cat, (long long)Mrows * 2 * DIMk, 2 * DIMk,
        q_mixw, (long long)DIMk * 3 * DIMk, 3 * DIMk, 0,
        nullptr, 0, p_posmix, Lk - 1,
        p_mix, nullptr, 0,
        Mrows, DIMk, 2 * DIMk, DIMk, 0, 5);
    // (13) double LN
    double_ln_kernel<<<Mrows, 256>>>(dn_g, dn_b, fn_g, fn_b);

    // (14,15) FFN
    tc_gemm<<<dim3(8, 64), 256, SB>>>(
        q_x2, (long long)Mrows * DIMk, DIMk,
        q_ffn1w, (long long)HIDk * DIMk, DIMk, 0,
        ffn_b1, 0, nullptr, 0,
        nullptr, q_hbuf, (long long)Mrows * HIDk,
        Mrows, HIDk, DIMk, HIDk, 0, 2);
    tc_gemm<<<dim3(4, 64), 256, SB>>>(
        q_hbuf, (long long)Mrows * HIDk, HIDk,
        q_ffn2w, (long long)DIMk * HIDk, HIDk, 0,
        ffn_b2, 0, p_dln, RMALL,
        out, nullptr, 0,
        Mrows, DIMk, HIDk, DIMk, 0, 3);
    (void)in_sizes; (void)n_in; (void)out_size;
}